// round 9
// baseline (speedup 1.0000x reference)
#include <cuda_runtime.h>
#include <cuda_bf16.h>
#include <cstdint>

#define BATCH 4
#define NPTS  4096
#define DIM   512
#define K_NB  10
#define KCAND 12

#define BM 128
#define BN 128
#define KC 64                // bf16 per K-chunk = 128 B per row
#define NSTAGE 4
#define A_BYTES (BM * 128)                  // 16 KB
#define STAGE_BYTES (2 * A_BYTES)           // 32 KB
#define N_KCHUNKS (DIM / KC)                // 8
#define SPAD 132

__device__ __align__(16) float g_Hn[(size_t)BATCH * NPTS * DIM];          // 32 MB fp32 normalized
__device__ __align__(16) __nv_bfloat16 g_Hbf[(size_t)BATCH * NPTS * DIM]; // 16 MB bf16
__device__ int g_cand[BATCH * NPTS * KCAND];
__device__ int g_topk[BATCH * NPTS * K_NB];

__device__ __forceinline__ uint32_t smem_u32(const void* p) {
    uint32_t a;
    asm("{ .reg .u64 t; cvta.to.shared.u64 t, %1; cvt.u32.u64 %0, t; }" : "=r"(a) : "l"(p));
    return a;
}
__device__ __forceinline__ void cp16(uint32_t dst, const void* src) {
    asm volatile("cp.async.cg.shared.global [%0], [%1], 16;" :: "r"(dst), "l"(src));
}
__device__ __forceinline__ void cp_commit() {
    asm volatile("cp.async.commit_group;" ::: "memory");
}
template <int N>
__device__ __forceinline__ void cp_wait() {
    asm volatile("cp.async.wait_group %0;" :: "n"(N) : "memory");
}
__device__ __forceinline__ void ldsm4(uint32_t* r, uint32_t addr) {
    asm volatile("ldmatrix.sync.aligned.m8n8.x4.shared.b16 {%0,%1,%2,%3}, [%4];"
                 : "=r"(r[0]), "=r"(r[1]), "=r"(r[2]), "=r"(r[3]) : "r"(addr));
}
__device__ __forceinline__ void mma16816(float* c, const uint32_t* a, uint32_t b0, uint32_t b1) {
    asm volatile(
        "mma.sync.aligned.m16n8k16.row.col.f32.bf16.bf16.f32 "
        "{%0,%1,%2,%3},{%4,%5,%6,%7},{%8,%9},{%0,%1,%2,%3};"
        : "+f"(c[0]), "+f"(c[1]), "+f"(c[2]), "+f"(c[3])
        : "r"(a[0]), "r"(a[1]), "r"(a[2]), "r"(a[3]), "r"(b0), "r"(b1));
}
__device__ __forceinline__ bool beats(float v, int vi, float w, int wi) {
    return (v > w) || (v == w && vi < wi);
}
__device__ __forceinline__ uint32_t fkey(float v) {
    uint32_t u = __float_as_uint(v);
    return (u & 0x80000000u) ? ~u : (u | 0x80000000u);
}
__device__ __forceinline__ float unkey(uint32_t u) {
    return (u & 0x80000000u) ? __uint_as_float(u & 0x7FFFFFFFu) : __uint_as_float(~u);
}

// ---------------------------------------------------------------------------
// K1: row-normalize -> fp32 g_Hn + bf16 g_Hbf (one warp per row)
// ---------------------------------------------------------------------------
__global__ void norm_kernel(const float* __restrict__ H) {
    int row = (blockIdx.x * blockDim.x + threadIdx.x) >> 5;
    int lane = threadIdx.x & 31;
    if (row >= BATCH * NPTS) return;
    const float4* src = (const float4*)(H + (size_t)row * DIM);
    float4* dstf = (float4*)(g_Hn + (size_t)row * DIM);
    __nv_bfloat16* dstb = g_Hbf + (size_t)row * DIM;
    float ss = 0.f;
    float4 v[4];
#pragma unroll
    for (int j = 0; j < 4; j++) {
        v[j] = src[lane + 32 * j];
        ss += v[j].x * v[j].x + v[j].y * v[j].y + v[j].z * v[j].z + v[j].w * v[j].w;
    }
#pragma unroll
    for (int o = 16; o; o >>= 1) ss += __shfl_xor_sync(0xffffffffu, ss, o);
    float inv = 1.0f / fmaxf(sqrtf(ss), 1e-12f);
#pragma unroll
    for (int j = 0; j < 4; j++) {
        float w[4] = {v[j].x * inv, v[j].y * inv, v[j].z * inv, v[j].w * inv};
        dstf[lane + 32 * j] = make_float4(w[0], w[1], w[2], w[3]);
        __nv_bfloat162 h0, h1;
        h0.x = __float2bfloat16_rn(w[0]); h0.y = __float2bfloat16_rn(w[1]);
        h1.x = __float2bfloat16_rn(w[2]); h1.y = __float2bfloat16_rn(w[3]);
        int off = 4 * lane + 128 * j;
        *(__nv_bfloat162*)(dstb + off) = h0;
        *(__nv_bfloat162*)(dstb + off + 2) = h1;
    }
}

// ---------------------------------------------------------------------------
// K2: symmetric bf16 GEMM -> sim in d_out.
//   Only tiles by >= bx compute; off-diagonal tiles also store the transpose.
//   grid (32, 32, 4); 256 threads; 2x4 warp grid; warp tile 64x32
// ---------------------------------------------------------------------------
__global__ void __launch_bounds__(256, 1) gemm_kernel(float* __restrict__ out) {
    const int bx = blockIdx.x, by = blockIdx.y;
    if (by < bx) return;                    // symmetry: compute upper triangle only

    extern __shared__ __align__(16) unsigned char rawsm[];
    unsigned char* dynp = (unsigned char*)(((uintptr_t)rawsm + 1023) & ~(uintptr_t)1023);
    const uint32_t smA = smem_u32(dynp);

    const int b = blockIdx.z;
    const int rowBase = bx * BM;
    const int colBase = by * BN;
    const int tid = threadIdx.x;
    const int warp = tid >> 5, lane = tid & 31;
    const int wM = warp >> 2, wN = warp & 3;

    const uint32_t aRowByte = (uint32_t)(wM * 64 + (lane & 15)) * 128;
    const uint32_t aK = (lane >> 4) * 16;
    const uint32_t bRowByte = (uint32_t)(wN * 32 + ((lane >> 4) << 3) + (lane & 7)) * 128;
    const uint32_t bK = ((lane >> 3) & 1) * 16;
    const uint32_t xr = (lane & 7) << 4;

    const __nv_bfloat16* __restrict__ gsrc = g_Hbf + (size_t)b * NPTS * DIM;

    const int ldRow0 = tid >> 3;
    const int ldSeg = tid & 7;
    const uint32_t ldDstOff = (uint32_t)(ldSeg * 16);

    auto issue_chunk = [&](int kc) {
        const uint32_t st = smA + (kc & (NSTAGE - 1)) * STAGE_BYTES;
        const int kin = kc * KC + ldSeg * 8;
#pragma unroll
        for (int i = 0; i < 4; i++) {
            int row = ldRow0 + 32 * i;
            uint32_t d = (uint32_t)row * 128 + (ldDstOff ^ ((row & 7) << 4));
            cp16(st + d, gsrc + (size_t)(rowBase + row) * DIM + kin);
            cp16(st + A_BYTES + d, gsrc + (size_t)(colBase + row) * DIM + kin);
        }
        cp_commit();
    };

    float acc[4][4][4];
#pragma unroll
    for (int mt = 0; mt < 4; mt++)
#pragma unroll
        for (int nt = 0; nt < 4; nt++)
#pragma unroll
            for (int q = 0; q < 4; q++) acc[mt][nt][q] = 0.f;

    issue_chunk(0); issue_chunk(1); issue_chunk(2);

    for (int kc = 0; kc < N_KCHUNKS; kc++) {
        const int rem = N_KCHUNKS - 1 - kc;
        if (rem >= 2) cp_wait<2>();
        else if (rem == 1) cp_wait<1>();
        else cp_wait<0>();
        __syncthreads();
        if (kc + 3 < N_KCHUNKS) issue_chunk(kc + 3);

        const uint32_t Ast = smA + (kc & (NSTAGE - 1)) * STAGE_BYTES;
        const uint32_t Bst = Ast + A_BYTES;
#pragma unroll
        for (int ks = 0; ks < KC / 16; ks++) {
            uint32_t a[4][4], bf[2][4];
#pragma unroll
            for (int mt = 0; mt < 4; mt++)
                ldsm4(a[mt], Ast + aRowByte + mt * 2048 + ((ks * 32 + aK) ^ xr));
#pragma unroll
            for (int np = 0; np < 2; np++)
                ldsm4(bf[np], Bst + bRowByte + np * 2048 + ((ks * 32 + bK) ^ xr));
#pragma unroll
            for (int mt = 0; mt < 4; mt++)
#pragma unroll
                for (int np = 0; np < 2; np++) {
                    mma16816(acc[mt][np * 2 + 0], a[mt], bf[np][0], bf[np][1]);
                    mma16816(acc[mt][np * 2 + 1], a[mt], bf[np][2], bf[np][3]);
                }
        }
    }
    __syncthreads();   // all stages consumed; reuse stage smem as epilogue tile

    float* Ssim = (float*)dynp;
    const int gid = lane >> 2, tig = lane & 3;

    // normal tile: rows rowBase+, cols colBase+
#pragma unroll
    for (int mt = 0; mt < 4; mt++) {
        const int r0 = wM * 64 + mt * 16 + gid;
#pragma unroll
        for (int nt = 0; nt < 4; nt++) {
            const int c = wN * 32 + nt * 8 + tig * 2;
            *(float2*)&Ssim[r0 * SPAD + c] = make_float2(acc[mt][nt][0], acc[mt][nt][1]);
            *(float2*)&Ssim[(r0 + 8) * SPAD + c] = make_float2(acc[mt][nt][2], acc[mt][nt][3]);
        }
    }
    __syncthreads();
#pragma unroll
    for (int it = 0; it < 16; it++) {
        int r = it * 8 + warp;
        float4 v = *(const float4*)&Ssim[r * SPAD + lane * 4];
        *(float4*)(out + ((size_t)b * NPTS + rowBase + r) * NPTS + colBase + lane * 4) = v;
    }

    if (bx == by) return;

    // transposed tile: rows colBase+, cols rowBase+
    __syncthreads();
#pragma unroll
    for (int mt = 0; mt < 4; mt++) {
        const int r0 = wM * 64 + mt * 16 + gid;
#pragma unroll
        for (int nt = 0; nt < 4; nt++) {
            const int c = wN * 32 + nt * 8 + tig * 2;
            Ssim[(c + 0) * SPAD + r0]     = acc[mt][nt][0];
            Ssim[(c + 1) * SPAD + r0]     = acc[mt][nt][1];
            Ssim[(c + 0) * SPAD + r0 + 8] = acc[mt][nt][2];
            Ssim[(c + 1) * SPAD + r0 + 8] = acc[mt][nt][3];
        }
    }
    __syncthreads();
#pragma unroll
    for (int it = 0; it < 16; it++) {
        int r = it * 8 + warp;
        float4 v = *(const float4*)&Ssim[r * SPAD + lane * 4];
        *(float4*)(out + ((size_t)b * NPTS + colBase + r) * NPTS + rowBase + lane * 4) = v;
    }
}

// ---------------------------------------------------------------------------
// K3: per-row streaming top-12 over sim + zero the sim buffer as we go
//   (one warp per row; replicated register list of packed uint64 keys)
// ---------------------------------------------------------------------------
__global__ void __launch_bounds__(256) scan_kernel(float* __restrict__ sim) {
    int row = (blockIdx.x * blockDim.x + threadIdx.x) >> 5;
    int lane = threadIdx.x & 31;
    if (row >= BATCH * NPTS) return;
    float4* srow = (float4*)(sim + (size_t)row * NPTS);

    const unsigned long long SENT = ((unsigned long long)fkey(-3.0e38f) << 32);
    unsigned long long L[KCAND];
#pragma unroll
    for (int j = 0; j < KCAND; j++) L[j] = SENT;
    float thresh = -3.0e38f;
    const float4 z = make_float4(0.f, 0.f, 0.f, 0.f);

    for (int it = 0; it < 32; it++) {
        float4 v4 = srow[lane + 32 * it];
        srow[lane + 32 * it] = z;          // fused zeroing of the output buffer
        float vv[4] = {v4.x, v4.y, v4.z, v4.w};
#pragma unroll
        for (int c = 0; c < 4; c++) {
            unsigned m = __ballot_sync(0xffffffffu, vv[c] >= thresh);
            while (m) {
                int src = __ffs(m) - 1;
                m &= m - 1;
                float cv = __shfl_sync(0xffffffffu, vv[c], src);
                if (!(cv >= thresh)) continue;     // thresh moved; prune
                int ci = src * 4 + c + 128 * it;
                unsigned long long key =
                    ((unsigned long long)fkey(cv) << 32) | (uint32_t)(~ci);
                unsigned long long carry = key;
#pragma unroll
                for (int j = 0; j < KCAND; j++) {
                    unsigned long long hi = (carry > L[j]) ? carry : L[j];
                    unsigned long long lo = (carry > L[j]) ? L[j] : carry;
                    L[j] = hi; carry = lo;
                }
                thresh = unkey((uint32_t)(L[KCAND - 1] >> 32));
            }
        }
    }
    if (lane == 0) {
        int* dst = g_cand + (size_t)row * KCAND;
#pragma unroll
        for (int j = 0; j < KCAND; j++)
            dst[j] = (int)(~(uint32_t)L[j]) & (NPTS - 1);   // safe-masked index
    }
}

// ---------------------------------------------------------------------------
// K4: exact fp32 rescore of 12 candidates -> top-10 (one warp per row)
// ---------------------------------------------------------------------------
__global__ void rescore_kernel() {
    int gw = (blockIdx.x * blockDim.x + threadIdx.x) >> 5;
    int lane = threadIdx.x & 31;
    if (gw >= BATCH * NPTS) return;
    const int b = gw >> 12;
    const float4* base = (const float4*)(g_Hn + (size_t)b * NPTS * DIM);
    const float4* myv = (const float4*)(g_Hn + (size_t)gw * DIM);

    float4 v[4];
#pragma unroll
    for (int j = 0; j < 4; j++) v[j] = myv[lane + 32 * j];

    int ci = (lane < KCAND) ? g_cand[(size_t)gw * KCAND + lane] : 0;

    float dots[KCAND];
#pragma unroll
    for (int c = 0; c < KCAND; c++) {
        int idx = __shfl_sync(0xffffffffu, ci, c) & (NPTS - 1);
        const float4* cv = base + (size_t)idx * (DIM / 4);
        float p = 0.f;
#pragma unroll
        for (int j = 0; j < 4; j++) {
            float4 u = cv[lane + 32 * j];
            p += v[j].x * u.x + v[j].y * u.y + v[j].z * u.z + v[j].w * u.w;
        }
#pragma unroll
        for (int o = 16; o; o >>= 1) p += __shfl_xor_sync(0xffffffffu, p, o);
        dots[c] = p;
    }

    if (lane == 0) {
        float lv[K_NB]; int li[K_NB];
#pragma unroll
        for (int j = 0; j < K_NB; j++) { lv[j] = -3.0e38f; li[j] = 0x7fffffff; }
        const int* cidx = g_cand + (size_t)gw * KCAND;
#pragma unroll
        for (int c = 0; c < KCAND; c++) {
            float cv = dots[c]; int cc = cidx[c];
            if (beats(cv, cc, lv[0], li[0])) {
                int j = 0;
                while (j < K_NB - 1 && beats(cv, cc, lv[j + 1], li[j + 1])) {
                    lv[j] = lv[j + 1]; li[j] = li[j + 1]; j++;
                }
                lv[j] = cv; li[j] = cc;
            }
        }
#pragma unroll
        for (int j = 0; j < K_NB; j++) g_topk[(size_t)gw * K_NB + j] = li[j];
    }
}

// ---------------------------------------------------------------------------
// K5: scatter s = 1/11 at top-k, +s at diagonal (buffer already zeroed by K3)
// ---------------------------------------------------------------------------
__global__ void scatter_kernel(float* __restrict__ out) {
    int row = blockIdx.x * blockDim.x + threadIdx.x;
    if (row >= BATCH * NPTS) return;
    int i = row & (NPTS - 1);
    float* dst = out + (size_t)row * NPTS;
    const int* idx = g_topk + (size_t)row * K_NB;
    const float s = 1.0f / 11.0f;
#pragma unroll
    for (int k = 0; k < K_NB; k++) dst[idx[k]] = s;
    dst[i] += s;
}

// ---------------------------------------------------------------------------
extern "C" void kernel_launch(void* const* d_in, const int* in_sizes, int n_in,
                              void* d_out, int out_size) {
    const float* H = (const float*)d_in[0];
    float* out = (float*)d_out;

    norm_kernel<<<(BATCH * NPTS * 32 + 255) / 256, 256>>>(H);

    const int smem_bytes = NSTAGE * STAGE_BYTES + 1024;   // epilogue reuses stages
    cudaFuncSetAttribute(gemm_kernel,
                         cudaFuncAttributeMaxDynamicSharedMemorySize, smem_bytes);
    dim3 gg(NPTS / BM, NPTS / BN, BATCH);
    gemm_kernel<<<gg, 256, smem_bytes>>>(out);   // sim -> d_out (scratch)

    scan_kernel<<<(BATCH * NPTS) / 8, 256>>>(out);   // top-12 + zeroes buffer

    rescore_kernel<<<(BATCH * NPTS * 32 + 255) / 256, 256>>>();

    scatter_kernel<<<(BATCH * NPTS + 255) / 256, 256>>>(out);
}

// round 10
// speedup vs baseline: 1.0042x; 1.0042x over previous
#include <cuda_runtime.h>
#include <cuda_bf16.h>
#include <cstdint>

#define BATCH 4
#define NPTS  4096
#define DIM   512
#define K_NB  10
#define KCAND 12

#define BM 128
#define BN 128
#define KC 64                // bf16 per K-chunk = 128 B per row
#define NSTAGE 4
#define A_BYTES (BM * 128)                  // 16 KB
#define STAGE_BYTES (2 * A_BYTES)           // 32 KB
#define N_KCHUNKS (DIM / KC)                // 8
#define SPAD 132

__device__ __align__(16) float g_Hn[(size_t)BATCH * NPTS * DIM];          // 32 MB fp32 normalized
__device__ __align__(16) __nv_bfloat16 g_Hbf[(size_t)BATCH * NPTS * DIM]; // 16 MB bf16
__device__ int g_cand[BATCH * NPTS * KCAND];
__device__ int g_topk[BATCH * NPTS * K_NB];

__device__ __forceinline__ uint32_t smem_u32(const void* p) {
    uint32_t a;
    asm("{ .reg .u64 t; cvta.to.shared.u64 t, %1; cvt.u32.u64 %0, t; }" : "=r"(a) : "l"(p));
    return a;
}
__device__ __forceinline__ void cp16(uint32_t dst, const void* src) {
    asm volatile("cp.async.cg.shared.global [%0], [%1], 16;" :: "r"(dst), "l"(src));
}
__device__ __forceinline__ void cp_commit() {
    asm volatile("cp.async.commit_group;" ::: "memory");
}
template <int N>
__device__ __forceinline__ void cp_wait() {
    asm volatile("cp.async.wait_group %0;" :: "n"(N) : "memory");
}
__device__ __forceinline__ void ldsm4(uint32_t* r, uint32_t addr) {
    asm volatile("ldmatrix.sync.aligned.m8n8.x4.shared.b16 {%0,%1,%2,%3}, [%4];"
                 : "=r"(r[0]), "=r"(r[1]), "=r"(r[2]), "=r"(r[3]) : "r"(addr));
}
__device__ __forceinline__ void mma16816(float* c, const uint32_t* a, uint32_t b0, uint32_t b1) {
    asm volatile(
        "mma.sync.aligned.m16n8k16.row.col.f32.bf16.bf16.f32 "
        "{%0,%1,%2,%3},{%4,%5,%6,%7},{%8,%9},{%0,%1,%2,%3};"
        : "+f"(c[0]), "+f"(c[1]), "+f"(c[2]), "+f"(c[3])
        : "r"(a[0]), "r"(a[1]), "r"(a[2]), "r"(a[3]), "r"(b0), "r"(b1));
}
__device__ __forceinline__ bool beats(float v, int vi, float w, int wi) {
    return (v > w) || (v == w && vi < wi);
}
__device__ __forceinline__ uint32_t fkey(float v) {
    uint32_t u = __float_as_uint(v);
    return (u & 0x80000000u) ? ~u : (u | 0x80000000u);
}
__device__ __forceinline__ float unkey(uint32_t u) {
    return (u & 0x80000000u) ? __uint_as_float(u & 0x7FFFFFFFu) : __uint_as_float(~u);
}

// ---------------------------------------------------------------------------
// K1: row-normalize -> fp32 g_Hn + bf16 g_Hbf (one warp per row)
// ---------------------------------------------------------------------------
__global__ void norm_kernel(const float* __restrict__ H) {
    int row = (blockIdx.x * blockDim.x + threadIdx.x) >> 5;
    int lane = threadIdx.x & 31;
    if (row >= BATCH * NPTS) return;
    const float4* src = (const float4*)(H + (size_t)row * DIM);
    float4* dstf = (float4*)(g_Hn + (size_t)row * DIM);
    __nv_bfloat16* dstb = g_Hbf + (size_t)row * DIM;
    float ss = 0.f;
    float4 v[4];
#pragma unroll
    for (int j = 0; j < 4; j++) {
        v[j] = src[lane + 32 * j];
        ss += v[j].x * v[j].x + v[j].y * v[j].y + v[j].z * v[j].z + v[j].w * v[j].w;
    }
#pragma unroll
    for (int o = 16; o; o >>= 1) ss += __shfl_xor_sync(0xffffffffu, ss, o);
    float inv = 1.0f / fmaxf(sqrtf(ss), 1e-12f);
#pragma unroll
    for (int j = 0; j < 4; j++) {
        float w[4] = {v[j].x * inv, v[j].y * inv, v[j].z * inv, v[j].w * inv};
        dstf[lane + 32 * j] = make_float4(w[0], w[1], w[2], w[3]);
        __nv_bfloat162 h0, h1;
        h0.x = __float2bfloat16_rn(w[0]); h0.y = __float2bfloat16_rn(w[1]);
        h1.x = __float2bfloat16_rn(w[2]); h1.y = __float2bfloat16_rn(w[3]);
        int off = 4 * lane + 128 * j;
        *(__nv_bfloat162*)(dstb + off) = h0;
        *(__nv_bfloat162*)(dstb + off + 2) = h1;
    }
}

// ---------------------------------------------------------------------------
// K2: symmetric bf16 GEMM -> sim in d_out.
//   Tiles by >= bx compute; acc dumped to BOTH smem layouts immediately
//   (normal + transposed) so acc dies right away -- no liveness across stores.
//   grid (32, 32, 4); 256 threads; 2x4 warp grid; warp tile 64x32
// ---------------------------------------------------------------------------
__global__ void __launch_bounds__(256, 1) gemm_kernel(float* __restrict__ out) {
    const int bx = blockIdx.x, by = blockIdx.y;
    if (by < bx) return;                    // symmetry: upper triangle only

    extern __shared__ __align__(16) unsigned char rawsm[];
    unsigned char* dynp = (unsigned char*)(((uintptr_t)rawsm + 1023) & ~(uintptr_t)1023);
    const uint32_t smA = smem_u32(dynp);

    const int b = blockIdx.z;
    const int rowBase = bx * BM;
    const int colBase = by * BN;
    const int tid = threadIdx.x;
    const int warp = tid >> 5, lane = tid & 31;
    const int wM = warp >> 2, wN = warp & 3;

    const uint32_t aRowByte = (uint32_t)(wM * 64 + (lane & 15)) * 128;
    const uint32_t aK = (lane >> 4) * 16;
    const uint32_t bRowByte = (uint32_t)(wN * 32 + ((lane >> 4) << 3) + (lane & 7)) * 128;
    const uint32_t bK = ((lane >> 3) & 1) * 16;
    const uint32_t xr = (lane & 7) << 4;

    const __nv_bfloat16* __restrict__ gsrc = g_Hbf + (size_t)b * NPTS * DIM;

    const int ldRow0 = tid >> 3;
    const int ldSeg = tid & 7;
    const uint32_t ldDstOff = (uint32_t)(ldSeg * 16);

    auto issue_chunk = [&](int kc) {
        const uint32_t st = smA + (kc & (NSTAGE - 1)) * STAGE_BYTES;
        const int kin = kc * KC + ldSeg * 8;
#pragma unroll
        for (int i = 0; i < 4; i++) {
            int row = ldRow0 + 32 * i;
            uint32_t d = (uint32_t)row * 128 + (ldDstOff ^ ((row & 7) << 4));
            cp16(st + d, gsrc + (size_t)(rowBase + row) * DIM + kin);
            cp16(st + A_BYTES + d, gsrc + (size_t)(colBase + row) * DIM + kin);
        }
        cp_commit();
    };

    float acc[4][4][4];
#pragma unroll
    for (int mt = 0; mt < 4; mt++)
#pragma unroll
        for (int nt = 0; nt < 4; nt++)
#pragma unroll
            for (int q = 0; q < 4; q++) acc[mt][nt][q] = 0.f;

    issue_chunk(0); issue_chunk(1); issue_chunk(2);

    for (int kc = 0; kc < N_KCHUNKS; kc++) {
        const int rem = N_KCHUNKS - 1 - kc;
        if (rem >= 2) cp_wait<2>();
        else if (rem == 1) cp_wait<1>();
        else cp_wait<0>();
        __syncthreads();
        if (kc + 3 < N_KCHUNKS) issue_chunk(kc + 3);

        const uint32_t Ast = smA + (kc & (NSTAGE - 1)) * STAGE_BYTES;
        const uint32_t Bst = Ast + A_BYTES;
#pragma unroll
        for (int ks = 0; ks < KC / 16; ks++) {
            uint32_t a[4][4], bf[2][4];
#pragma unroll
            for (int mt = 0; mt < 4; mt++)
                ldsm4(a[mt], Ast + aRowByte + mt * 2048 + ((ks * 32 + aK) ^ xr));
#pragma unroll
            for (int np = 0; np < 2; np++)
                ldsm4(bf[np], Bst + bRowByte + np * 2048 + ((ks * 32 + bK) ^ xr));
#pragma unroll
            for (int mt = 0; mt < 4; mt++)
#pragma unroll
                for (int np = 0; np < 2; np++) {
                    mma16816(acc[mt][np * 2 + 0], a[mt], bf[np][0], bf[np][1]);
                    mma16816(acc[mt][np * 2 + 1], a[mt], bf[np][2], bf[np][3]);
                }
        }
    }
    __syncthreads();   // all stages consumed; reuse stage smem for epilogue

    float* Ssim  = (float*)dynp;             // [BM][SPAD] normal layout
    float* SsimT = Ssim + BM * SPAD;         // [BN][SPAD] transposed layout
    const int gid = lane >> 2, tig = lane & 3;
    const bool diag = (bx == by);

    // dump acc to BOTH layouts back-to-back; acc dead after this block
#pragma unroll
    for (int mt = 0; mt < 4; mt++) {
        const int r0 = wM * 64 + mt * 16 + gid;
#pragma unroll
        for (int nt = 0; nt < 4; nt++) {
            const int c = wN * 32 + nt * 8 + tig * 2;
            *(float2*)&Ssim[r0 * SPAD + c] = make_float2(acc[mt][nt][0], acc[mt][nt][1]);
            *(float2*)&Ssim[(r0 + 8) * SPAD + c] = make_float2(acc[mt][nt][2], acc[mt][nt][3]);
            if (!diag) {
                SsimT[(c + 0) * SPAD + r0]     = acc[mt][nt][0];
                SsimT[(c + 1) * SPAD + r0]     = acc[mt][nt][1];
                SsimT[(c + 0) * SPAD + r0 + 8] = acc[mt][nt][2];
                SsimT[(c + 1) * SPAD + r0 + 8] = acc[mt][nt][3];
            }
        }
    }
    __syncthreads();

    // coalesced copies: smem row -> global row
#pragma unroll
    for (int it = 0; it < 16; it++) {
        int r = it * 8 + warp;
        float4 v = *(const float4*)&Ssim[r * SPAD + lane * 4];
        *(float4*)(out + ((size_t)b * NPTS + rowBase + r) * NPTS + colBase + lane * 4) = v;
    }
    if (!diag) {
#pragma unroll
        for (int it = 0; it < 16; it++) {
            int r = it * 8 + warp;
            float4 v = *(const float4*)&SsimT[r * SPAD + lane * 4];
            *(float4*)(out + ((size_t)b * NPTS + colBase + r) * NPTS + rowBase + lane * 4) = v;
        }
    }
}

// ---------------------------------------------------------------------------
// K3: per-row streaming top-12 over sim + fused zeroing (one warp per row)
// ---------------------------------------------------------------------------
__global__ void __launch_bounds__(256) scan_kernel(float* __restrict__ sim) {
    int row = (blockIdx.x * blockDim.x + threadIdx.x) >> 5;
    int lane = threadIdx.x & 31;
    if (row >= BATCH * NPTS) return;
    float4* srow = (float4*)(sim + (size_t)row * NPTS);

    const unsigned long long SENT = ((unsigned long long)fkey(-3.0e38f) << 32);
    unsigned long long L[KCAND];
#pragma unroll
    for (int j = 0; j < KCAND; j++) L[j] = SENT;
    float thresh = -3.0e38f;
    const float4 z = make_float4(0.f, 0.f, 0.f, 0.f);

    for (int it = 0; it < 32; it++) {
        float4 v4 = srow[lane + 32 * it];
        srow[lane + 32 * it] = z;          // fused zeroing of the output buffer
        float vv[4] = {v4.x, v4.y, v4.z, v4.w};
#pragma unroll
        for (int c = 0; c < 4; c++) {
            unsigned m = __ballot_sync(0xffffffffu, vv[c] >= thresh);
            while (m) {
                int src = __ffs(m) - 1;
                m &= m - 1;
                float cv = __shfl_sync(0xffffffffu, vv[c], src);
                if (!(cv >= thresh)) continue;     // thresh moved; prune
                int ci = src * 4 + c + 128 * it;
                unsigned long long key =
                    ((unsigned long long)fkey(cv) << 32) | (uint32_t)(~ci);
                unsigned long long carry = key;
#pragma unroll
                for (int j = 0; j < KCAND; j++) {
                    unsigned long long hi = (carry > L[j]) ? carry : L[j];
                    unsigned long long lo = (carry > L[j]) ? L[j] : carry;
                    L[j] = hi; carry = lo;
                }
                thresh = unkey((uint32_t)(L[KCAND - 1] >> 32));
            }
        }
    }
    if (lane == 0) {
        int* dst = g_cand + (size_t)row * KCAND;
#pragma unroll
        for (int j = 0; j < KCAND; j++)
            dst[j] = (int)(~(uint32_t)L[j]) & (NPTS - 1);   // safe-masked index
    }
}

// ---------------------------------------------------------------------------
// K4: exact fp32 rescore of 12 candidates -> top-10 (one warp per row)
// ---------------------------------------------------------------------------
__global__ void rescore_kernel() {
    int gw = (blockIdx.x * blockDim.x + threadIdx.x) >> 5;
    int lane = threadIdx.x & 31;
    if (gw >= BATCH * NPTS) return;
    const int b = gw >> 12;
    const float4* base = (const float4*)(g_Hn + (size_t)b * NPTS * DIM);
    const float4* myv = (const float4*)(g_Hn + (size_t)gw * DIM);

    float4 v[4];
#pragma unroll
    for (int j = 0; j < 4; j++) v[j] = myv[lane + 32 * j];

    int ci = (lane < KCAND) ? g_cand[(size_t)gw * KCAND + lane] : 0;

    float dots[KCAND];
#pragma unroll
    for (int c = 0; c < KCAND; c++) {
        int idx = __shfl_sync(0xffffffffu, ci, c) & (NPTS - 1);
        const float4* cv = base + (size_t)idx * (DIM / 4);
        float p = 0.f;
#pragma unroll
        for (int j = 0; j < 4; j++) {
            float4 u = cv[lane + 32 * j];
            p += v[j].x * u.x + v[j].y * u.y + v[j].z * u.z + v[j].w * u.w;
        }
#pragma unroll
        for (int o = 16; o; o >>= 1) p += __shfl_xor_sync(0xffffffffu, p, o);
        dots[c] = p;
    }

    if (lane == 0) {
        float lv[K_NB]; int li[K_NB];
#pragma unroll
        for (int j = 0; j < K_NB; j++) { lv[j] = -3.0e38f; li[j] = 0x7fffffff; }
        const int* cidx = g_cand + (size_t)gw * KCAND;
#pragma unroll
        for (int c = 0; c < KCAND; c++) {
            float cv = dots[c]; int cc = cidx[c];
            if (beats(cv, cc, lv[0], li[0])) {
                int j = 0;
                while (j < K_NB - 1 && beats(cv, cc, lv[j + 1], li[j + 1])) {
                    lv[j] = lv[j + 1]; li[j] = li[j + 1]; j++;
                }
                lv[j] = cv; li[j] = cc;
            }
        }
#pragma unroll
        for (int j = 0; j < K_NB; j++) g_topk[(size_t)gw * K_NB + j] = li[j];
    }
}

// ---------------------------------------------------------------------------
// K5: scatter s = 1/11 at top-k, +s at diagonal (buffer already zeroed by K3)
// ---------------------------------------------------------------------------
__global__ void scatter_kernel(float* __restrict__ out) {
    int row = blockIdx.x * blockDim.x + threadIdx.x;
    if (row >= BATCH * NPTS) return;
    int i = row & (NPTS - 1);
    float* dst = out + (size_t)row * NPTS;
    const int* idx = g_topk + (size_t)row * K_NB;
    const float s = 1.0f / 11.0f;
#pragma unroll
    for (int k = 0; k < K_NB; k++) dst[idx[k]] = s;
    dst[i] += s;
}

// ---------------------------------------------------------------------------
extern "C" void kernel_launch(void* const* d_in, const int* in_sizes, int n_in,
                              void* d_out, int out_size) {
    const float* H = (const float*)d_in[0];
    float* out = (float*)d_out;

    norm_kernel<<<(BATCH * NPTS * 32 + 255) / 256, 256>>>(H);

    // smem: stages (128 KB) overlapped with epilogue (2 x BM x SPAD floats)
    const int smem_bytes = 2 * BM * SPAD * 4 + 1024;   // 136,192 B > stage区 131,072
    cudaFuncSetAttribute(gemm_kernel,
                         cudaFuncAttributeMaxDynamicSharedMemorySize, smem_bytes);
    dim3 gg(NPTS / BM, NPTS / BN, BATCH);
    gemm_kernel<<<gg, 256, smem_bytes>>>(out);   // sim -> d_out (scratch)

    scan_kernel<<<(BATCH * NPTS) / 8, 256>>>(out);   // top-12 + zeroes buffer

    rescore_kernel<<<(BATCH * NPTS * 32 + 255) / 256, 256>>>();

    scatter_kernel<<<(BATCH * NPTS + 255) / 256, 256>>>(out);
}

// round 11
// speedup vs baseline: 2.3138x; 2.3042x over previous
#include <cuda_runtime.h>
#include <cuda_bf16.h>
#include <cstdint>

#define BATCH 4
#define NPTS  4096
#define DIM   512
#define K_NB  10
#define KCAND 12

#define BM 128
#define BN 128
#define KC 64                // bf16 per K-chunk = 128 B per row
#define NSTAGE 4
#define A_BYTES (BM * 128)                  // 16 KB
#define STAGE_BYTES (2 * A_BYTES)           // 32 KB
#define N_KCHUNKS (DIM / DIM * 8)           // 8 (DIM/KC)
#define SPAD 132
#define SCHUNK 128                          // float4 per scan chunk (2 KB)

__device__ __align__(16) float g_Hn[(size_t)BATCH * NPTS * DIM];          // 32 MB fp32 normalized
__device__ __align__(16) __nv_bfloat16 g_Hbf[(size_t)BATCH * NPTS * DIM]; // 16 MB bf16
__device__ int g_cand[BATCH * NPTS * KCAND];
__device__ int g_topk[BATCH * NPTS * K_NB];

__device__ __forceinline__ uint32_t smem_u32(const void* p) {
    uint32_t a;
    asm("{ .reg .u64 t; cvta.to.shared.u64 t, %1; cvt.u32.u64 %0, t; }" : "=r"(a) : "l"(p));
    return a;
}
__device__ __forceinline__ void cp16(uint32_t dst, const void* src) {
    asm volatile("cp.async.cg.shared.global [%0], [%1], 16;" :: "r"(dst), "l"(src));
}
__device__ __forceinline__ void cp_commit() {
    asm volatile("cp.async.commit_group;" ::: "memory");
}
template <int N>
__device__ __forceinline__ void cp_wait() {
    asm volatile("cp.async.wait_group %0;" :: "n"(N) : "memory");
}
__device__ __forceinline__ void ldsm4(uint32_t* r, uint32_t addr) {
    asm volatile("ldmatrix.sync.aligned.m8n8.x4.shared.b16 {%0,%1,%2,%3}, [%4];"
                 : "=r"(r[0]), "=r"(r[1]), "=r"(r[2]), "=r"(r[3]) : "r"(addr));
}
__device__ __forceinline__ void mma16816(float* c, const uint32_t* a, uint32_t b0, uint32_t b1) {
    asm volatile(
        "mma.sync.aligned.m16n8k16.row.col.f32.bf16.bf16.f32 "
        "{%0,%1,%2,%3},{%4,%5,%6,%7},{%8,%9},{%0,%1,%2,%3};"
        : "+f"(c[0]), "+f"(c[1]), "+f"(c[2]), "+f"(c[3])
        : "r"(a[0]), "r"(a[1]), "r"(a[2]), "r"(a[3]), "r"(b0), "r"(b1));
}
__device__ __forceinline__ bool beats(float v, int vi, float w, int wi) {
    return (v > w) || (v == w && vi < wi);
}
__device__ __forceinline__ uint32_t fkey(float v) {
    uint32_t u = __float_as_uint(v);
    return (u & 0x80000000u) ? ~u : (u | 0x80000000u);
}
__device__ __forceinline__ float unkey(uint32_t u) {
    return (u & 0x80000000u) ? __uint_as_float(u & 0x7FFFFFFFu) : __uint_as_float(~u);
}

// ---------------------------------------------------------------------------
// K1: row-normalize -> fp32 g_Hn + bf16 g_Hbf (one warp per row)
// ---------------------------------------------------------------------------
__global__ void norm_kernel(const float* __restrict__ H) {
    int row = (blockIdx.x * blockDim.x + threadIdx.x) >> 5;
    int lane = threadIdx.x & 31;
    if (row >= BATCH * NPTS) return;
    const float4* src = (const float4*)(H + (size_t)row * DIM);
    float4* dstf = (float4*)(g_Hn + (size_t)row * DIM);
    __nv_bfloat16* dstb = g_Hbf + (size_t)row * DIM;
    float ss = 0.f;
    float4 v[4];
#pragma unroll
    for (int j = 0; j < 4; j++) {
        v[j] = src[lane + 32 * j];
        ss += v[j].x * v[j].x + v[j].y * v[j].y + v[j].z * v[j].z + v[j].w * v[j].w;
    }
#pragma unroll
    for (int o = 16; o; o >>= 1) ss += __shfl_xor_sync(0xffffffffu, ss, o);
    float inv = 1.0f / fmaxf(sqrtf(ss), 1e-12f);
#pragma unroll
    for (int j = 0; j < 4; j++) {
        float w[4] = {v[j].x * inv, v[j].y * inv, v[j].z * inv, v[j].w * inv};
        dstf[lane + 32 * j] = make_float4(w[0], w[1], w[2], w[3]);
        __nv_bfloat162 h0, h1;
        h0.x = __float2bfloat16_rn(w[0]); h0.y = __float2bfloat16_rn(w[1]);
        h1.x = __float2bfloat16_rn(w[2]); h1.y = __float2bfloat16_rn(w[3]);
        int off = 4 * lane + 128 * j;
        *(__nv_bfloat162*)(dstb + off) = h0;
        *(__nv_bfloat162*)(dstb + off + 2) = h1;
    }
}

// ---------------------------------------------------------------------------
// K2: pure bf16 mma.sync GEMM tile -> sim written into d_out  (R8-proven)
//   grid (32, 32, 4); 256 threads; 2x4 warp grid; warp tile 64x32
// ---------------------------------------------------------------------------
__global__ void __launch_bounds__(256, 1) gemm_kernel(float* __restrict__ out) {
    extern __shared__ __align__(16) unsigned char rawsm[];
    unsigned char* dynp = (unsigned char*)(((uintptr_t)rawsm + 1023) & ~(uintptr_t)1023);
    const uint32_t smA = smem_u32(dynp);

    const int b = blockIdx.z;
    const int rowBase = blockIdx.x * BM;
    const int colBase = blockIdx.y * BN;
    const int tid = threadIdx.x;
    const int warp = tid >> 5, lane = tid & 31;
    const int wM = warp >> 2, wN = warp & 3;

    const uint32_t aRowByte = (uint32_t)(wM * 64 + (lane & 15)) * 128;
    const uint32_t aK = (lane >> 4) * 16;
    const uint32_t bRowByte = (uint32_t)(wN * 32 + ((lane >> 4) << 3) + (lane & 7)) * 128;
    const uint32_t bK = ((lane >> 3) & 1) * 16;
    const uint32_t xr = (lane & 7) << 4;

    const __nv_bfloat16* __restrict__ gsrc = g_Hbf + (size_t)b * NPTS * DIM;

    const int ldRow0 = tid >> 3;
    const int ldSeg = tid & 7;
    const uint32_t ldDstOff = (uint32_t)(ldSeg * 16);

    auto issue_chunk = [&](int kc) {
        const uint32_t st = smA + (kc & (NSTAGE - 1)) * STAGE_BYTES;
        const int kin = kc * KC + ldSeg * 8;
#pragma unroll
        for (int i = 0; i < 4; i++) {
            int row = ldRow0 + 32 * i;
            uint32_t d = (uint32_t)row * 128 + (ldDstOff ^ ((row & 7) << 4));
            cp16(st + d, gsrc + (size_t)(rowBase + row) * DIM + kin);
            cp16(st + A_BYTES + d, gsrc + (size_t)(colBase + row) * DIM + kin);
        }
        cp_commit();
    };

    float acc[4][4][4];
#pragma unroll
    for (int mt = 0; mt < 4; mt++)
#pragma unroll
        for (int nt = 0; nt < 4; nt++)
#pragma unroll
            for (int q = 0; q < 4; q++) acc[mt][nt][q] = 0.f;

    issue_chunk(0); issue_chunk(1); issue_chunk(2);

    for (int kc = 0; kc < 8; kc++) {
        const int rem = 7 - kc;
        if (rem >= 2) cp_wait<2>();
        else if (rem == 1) cp_wait<1>();
        else cp_wait<0>();
        __syncthreads();
        if (kc + 3 < 8) issue_chunk(kc + 3);

        const uint32_t Ast = smA + (kc & (NSTAGE - 1)) * STAGE_BYTES;
        const uint32_t Bst = Ast + A_BYTES;
#pragma unroll
        for (int ks = 0; ks < KC / 16; ks++) {
            uint32_t a[4][4], bf[2][4];
#pragma unroll
            for (int mt = 0; mt < 4; mt++)
                ldsm4(a[mt], Ast + aRowByte + mt * 2048 + ((ks * 32 + aK) ^ xr));
#pragma unroll
            for (int np = 0; np < 2; np++)
                ldsm4(bf[np], Bst + bRowByte + np * 2048 + ((ks * 32 + bK) ^ xr));
#pragma unroll
            for (int mt = 0; mt < 4; mt++)
#pragma unroll
                for (int np = 0; np < 2; np++) {
                    mma16816(acc[mt][np * 2 + 0], a[mt], bf[np][0], bf[np][1]);
                    mma16816(acc[mt][np * 2 + 1], a[mt], bf[np][2], bf[np][3]);
                }
        }
    }
    __syncthreads();   // all stages consumed; reuse stage smem as epilogue tile

    float* Ssim = (float*)dynp;
    const int gid = lane >> 2, tig = lane & 3;
#pragma unroll
    for (int mt = 0; mt < 4; mt++) {
        const int r0 = wM * 64 + mt * 16 + gid;
#pragma unroll
        for (int nt = 0; nt < 4; nt++) {
            const int c = wN * 32 + nt * 8 + tig * 2;
            *(float2*)&Ssim[r0 * SPAD + c] = make_float2(acc[mt][nt][0], acc[mt][nt][1]);
            *(float2*)&Ssim[(r0 + 8) * SPAD + c] = make_float2(acc[mt][nt][2], acc[mt][nt][3]);
        }
    }
    __syncthreads();

#pragma unroll
    for (int it = 0; it < 16; it++) {
        int r = it * 8 + warp;
        float4 v = *(const float4*)&Ssim[r * SPAD + lane * 4];
        *(float4*)(out + ((size_t)b * NPTS + rowBase + r) * NPTS + colBase + lane * 4) = v;
    }
}

// ---------------------------------------------------------------------------
// K3: per-row streaming top-12, cp.async double-buffered (one warp per row)
//   Each lane cp.asyncs exactly the smem entries it later reads -> per-thread
//   wait_group is sufficient, no barriers in the stream loop.
// ---------------------------------------------------------------------------
__global__ void __launch_bounds__(256) scan_kernel(const float* __restrict__ sim) {
    __shared__ __align__(16) float4 sbuf[8][2][SCHUNK];   // 32 KB
    const int wid = threadIdx.x >> 5;
    const int lane = threadIdx.x & 31;
    const int row = blockIdx.x * 8 + wid;
    const float4* srow = (const float4*)(sim + (size_t)row * NPTS);

    auto prefetch = [&](int ch) {
        const int buf = ch & 1;
#pragma unroll
        for (int q = 0; q < 4; q++)
            cp16(smem_u32(&sbuf[wid][buf][lane + 32 * q]), srow + ch * SCHUNK + lane + 32 * q);
        cp_commit();
    };

    const unsigned long long SENT = ((unsigned long long)fkey(-3.0e38f) << 32);
    unsigned long long L[KCAND];
#pragma unroll
    for (int j = 0; j < KCAND; j++) L[j] = SENT;
    float thresh = -3.0e38f;

    prefetch(0);
    for (int ch = 0; ch < 8; ch++) {
        if (ch + 1 < 8) { prefetch(ch + 1); cp_wait<1>(); }
        else cp_wait<0>();
        const int buf = ch & 1;
#pragma unroll
        for (int q = 0; q < 4; q++) {
            float4 v4 = sbuf[wid][buf][lane + 32 * q];
            float vv[4] = {v4.x, v4.y, v4.z, v4.w};
#pragma unroll
            for (int c = 0; c < 4; c++) {
                unsigned m = __ballot_sync(0xffffffffu, vv[c] >= thresh);
                while (m) {
                    int src = __ffs(m) - 1;
                    m &= m - 1;
                    float cv = __shfl_sync(0xffffffffu, vv[c], src);
                    if (!(cv >= thresh)) continue;     // thresh moved; prune
                    int ci = ch * 512 + q * 128 + src * 4 + c;
                    unsigned long long key =
                        ((unsigned long long)fkey(cv) << 32) | (uint32_t)(~ci);
                    unsigned long long carry = key;
#pragma unroll
                    for (int j = 0; j < KCAND; j++) {
                        unsigned long long hi = (carry > L[j]) ? carry : L[j];
                        unsigned long long lo = (carry > L[j]) ? L[j] : carry;
                        L[j] = hi; carry = lo;
                    }
                    thresh = unkey((uint32_t)(L[KCAND - 1] >> 32));
                }
            }
        }
    }
    if (lane == 0) {
        int* dst = g_cand + (size_t)row * KCAND;
#pragma unroll
        for (int j = 0; j < KCAND; j++)
            dst[j] = (int)(~(uint32_t)L[j]) & (NPTS - 1);
    }
}

// ---------------------------------------------------------------------------
// K4: exact fp32 rescore of 12 candidates -> top-10 (one warp per row)
// ---------------------------------------------------------------------------
__global__ void __launch_bounds__(256, 2) rescore_kernel() {
    int gw = (blockIdx.x * blockDim.x + threadIdx.x) >> 5;
    int lane = threadIdx.x & 31;
    if (gw >= BATCH * NPTS) return;
    const int b = gw >> 12;
    const float4* base = (const float4*)(g_Hn + (size_t)b * NPTS * DIM);
    const float4* myv = (const float4*)(g_Hn + (size_t)gw * DIM);

    float4 v[4];
#pragma unroll
    for (int j = 0; j < 4; j++) v[j] = myv[lane + 32 * j];

    int ci = (lane < KCAND) ? g_cand[(size_t)gw * KCAND + lane] : 0;

    float dots[KCAND];
#pragma unroll
    for (int c = 0; c < KCAND; c++) {
        int idx = __shfl_sync(0xffffffffu, ci, c) & (NPTS - 1);
        const float4* cv = base + (size_t)idx * (DIM / 4);
        float p = 0.f;
#pragma unroll
        for (int j = 0; j < 4; j++) {
            float4 u = cv[lane + 32 * j];
            p += v[j].x * u.x + v[j].y * u.y + v[j].z * u.z + v[j].w * u.w;
        }
#pragma unroll
        for (int o = 16; o; o >>= 1) p += __shfl_xor_sync(0xffffffffu, p, o);
        dots[c] = p;
    }

    if (lane == 0) {
        float lv[K_NB]; int li[K_NB];
#pragma unroll
        for (int j = 0; j < K_NB; j++) { lv[j] = -3.0e38f; li[j] = 0x7fffffff; }
        const int* cidx = g_cand + (size_t)gw * KCAND;
#pragma unroll
        for (int c = 0; c < KCAND; c++) {
            float cv = dots[c]; int cc = cidx[c];
            if (beats(cv, cc, lv[0], li[0])) {
                int j = 0;
                while (j < K_NB - 1 && beats(cv, cc, lv[j + 1], li[j + 1])) {
                    lv[j] = lv[j + 1]; li[j] = li[j + 1]; j++;
                }
                lv[j] = cv; li[j] = cc;
            }
        }
#pragma unroll
        for (int j = 0; j < K_NB; j++) g_topk[(size_t)gw * K_NB + j] = li[j];
    }
}

// ---------------------------------------------------------------------------
// K5: zero output; K6: scatter s = 1/11 (+s at diagonal)
// ---------------------------------------------------------------------------
__global__ void zero_kernel(float4* __restrict__ out, size_t n4) {
    size_t i = (size_t)blockIdx.x * blockDim.x + threadIdx.x;
    size_t stride = (size_t)gridDim.x * blockDim.x;
    float4 z = make_float4(0.f, 0.f, 0.f, 0.f);
    for (; i < n4; i += stride) out[i] = z;
}

__global__ void scatter_kernel(float* __restrict__ out) {
    int row = blockIdx.x * blockDim.x + threadIdx.x;
    if (row >= BATCH * NPTS) return;
    int i = row & (NPTS - 1);
    float* dst = out + (size_t)row * NPTS;
    const int* idx = g_topk + (size_t)row * K_NB;
    const float s = 1.0f / 11.0f;
#pragma unroll
    for (int k = 0; k < K_NB; k++) dst[idx[k]] = s;
    dst[i] += s;
}

// ---------------------------------------------------------------------------
extern "C" void kernel_launch(void* const* d_in, const int* in_sizes, int n_in,
                              void* d_out, int out_size) {
    const float* H = (const float*)d_in[0];
    float* out = (float*)d_out;

    norm_kernel<<<(BATCH * NPTS * 32 + 255) / 256, 256>>>(H);

    const int smem_bytes = NSTAGE * STAGE_BYTES + 1024;
    cudaFuncSetAttribute(gemm_kernel,
                         cudaFuncAttributeMaxDynamicSharedMemorySize, smem_bytes);
    dim3 gg(NPTS / BM, NPTS / BN, BATCH);
    gemm_kernel<<<gg, 256, smem_bytes>>>(out);   // sim -> d_out (scratch)

    scan_kernel<<<(BATCH * NPTS) / 8, 256>>>(out);

    rescore_kernel<<<(BATCH * NPTS * 32 + 255) / 256, 256>>>();

    size_t n4 = (size_t)BATCH * NPTS * NPTS / 4;
    zero_kernel<<<16384, 256>>>((float4*)out, n4);

    scatter_kernel<<<(BATCH * NPTS + 255) / 256, 256>>>(out);
}

// round 12
// speedup vs baseline: 2.4101x; 1.0416x over previous
#include <cuda_runtime.h>
#include <cuda_bf16.h>
#include <cstdint>

#define BATCH 4
#define NPTS  4096
#define DIM   512
#define K_NB  10
#define KCAND 12

#define BM 128
#define BN 256
#define KC 64                 // bf16 per K-chunk = 128 B per row
#define NSTAGE 3
#define A_BYTES (BM * 128)                  // 16 KB
#define B_BYTES (BN * 128)                  // 32 KB
#define STAGE_BYTES (A_BYTES + B_BYTES)     // 48 KB
#define NKC 8                               // DIM/KC
#define SPAD 260
#define SCHUNK 128                          // float4 per scan chunk (2 KB)

__device__ __align__(16) float g_Hn[(size_t)BATCH * NPTS * DIM];          // 32 MB fp32 normalized
__device__ __align__(16) __nv_bfloat16 g_Hbf[(size_t)BATCH * NPTS * DIM]; // 16 MB bf16
__device__ int g_cand[BATCH * NPTS * KCAND];
__device__ int g_topk[BATCH * NPTS * K_NB];

__device__ __forceinline__ uint32_t smem_u32(const void* p) {
    uint32_t a;
    asm("{ .reg .u64 t; cvta.to.shared.u64 t, %1; cvt.u32.u64 %0, t; }" : "=r"(a) : "l"(p));
    return a;
}
__device__ __forceinline__ void cp16(uint32_t dst, const void* src) {
    asm volatile("cp.async.cg.shared.global [%0], [%1], 16;" :: "r"(dst), "l"(src));
}
__device__ __forceinline__ void cp_commit() {
    asm volatile("cp.async.commit_group;" ::: "memory");
}
template <int N>
__device__ __forceinline__ void cp_wait() {
    asm volatile("cp.async.wait_group %0;" :: "n"(N) : "memory");
}
__device__ __forceinline__ void ldsm4(uint32_t* r, uint32_t addr) {
    asm volatile("ldmatrix.sync.aligned.m8n8.x4.shared.b16 {%0,%1,%2,%3}, [%4];"
                 : "=r"(r[0]), "=r"(r[1]), "=r"(r[2]), "=r"(r[3]) : "r"(addr));
}
__device__ __forceinline__ void mma16816(float* c, const uint32_t* a, uint32_t b0, uint32_t b1) {
    asm volatile(
        "mma.sync.aligned.m16n8k16.row.col.f32.bf16.bf16.f32 "
        "{%0,%1,%2,%3},{%4,%5,%6,%7},{%8,%9},{%0,%1,%2,%3};"
        : "+f"(c[0]), "+f"(c[1]), "+f"(c[2]), "+f"(c[3])
        : "r"(a[0]), "r"(a[1]), "r"(a[2]), "r"(a[3]), "r"(b0), "r"(b1));
}
__device__ __forceinline__ bool beats(float v, int vi, float w, int wi) {
    return (v > w) || (v == w && vi < wi);
}
__device__ __forceinline__ uint32_t fkey(float v) {
    uint32_t u = __float_as_uint(v);
    return (u & 0x80000000u) ? ~u : (u | 0x80000000u);
}
__device__ __forceinline__ float unkey(uint32_t u) {
    return (u & 0x80000000u) ? __uint_as_float(u & 0x7FFFFFFFu) : __uint_as_float(~u);
}

// ---------------------------------------------------------------------------
// K1: row-normalize -> fp32 g_Hn + bf16 g_Hbf (one warp per row)
// ---------------------------------------------------------------------------
__global__ void norm_kernel(const float* __restrict__ H) {
    int row = (blockIdx.x * blockDim.x + threadIdx.x) >> 5;
    int lane = threadIdx.x & 31;
    if (row >= BATCH * NPTS) return;
    const float4* src = (const float4*)(H + (size_t)row * DIM);
    float4* dstf = (float4*)(g_Hn + (size_t)row * DIM);
    __nv_bfloat16* dstb = g_Hbf + (size_t)row * DIM;
    float ss = 0.f;
    float4 v[4];
#pragma unroll
    for (int j = 0; j < 4; j++) {
        v[j] = src[lane + 32 * j];
        ss += v[j].x * v[j].x + v[j].y * v[j].y + v[j].z * v[j].z + v[j].w * v[j].w;
    }
#pragma unroll
    for (int o = 16; o; o >>= 1) ss += __shfl_xor_sync(0xffffffffu, ss, o);
    float inv = 1.0f / fmaxf(sqrtf(ss), 1e-12f);
#pragma unroll
    for (int j = 0; j < 4; j++) {
        float w[4] = {v[j].x * inv, v[j].y * inv, v[j].z * inv, v[j].w * inv};
        dstf[lane + 32 * j] = make_float4(w[0], w[1], w[2], w[3]);
        __nv_bfloat162 h0, h1;
        h0.x = __float2bfloat16_rn(w[0]); h0.y = __float2bfloat16_rn(w[1]);
        h1.x = __float2bfloat16_rn(w[2]); h1.y = __float2bfloat16_rn(w[3]);
        int off = 4 * lane + 128 * j;
        *(__nv_bfloat162*)(dstb + off) = h0;
        *(__nv_bfloat162*)(dstb + off + 2) = h1;
    }
}

// ---------------------------------------------------------------------------
// K2: bf16 mma.sync GEMM, 128x256 CTA tile, 512 threads (16 warps: 2Mx8N)
//   4 warps/SMSP for latency hiding; 3-stage cp.async; sim -> d_out
// ---------------------------------------------------------------------------
__global__ void __launch_bounds__(512, 1) gemm_kernel(float* __restrict__ out) {
    extern __shared__ __align__(16) unsigned char rawsm[];
    unsigned char* dynp = (unsigned char*)(((uintptr_t)rawsm + 1023) & ~(uintptr_t)1023);
    const uint32_t smA = smem_u32(dynp);

    const int b = blockIdx.z;
    const int rowBase = blockIdx.x * BM;
    const int colBase = blockIdx.y * BN;
    const int tid = threadIdx.x;
    const int warp = tid >> 5, lane = tid & 31;
    const int wM = warp >> 3, wN = warp & 7;

    const uint32_t aRowByte = (uint32_t)(wM * 64 + (lane & 15)) * 128;
    const uint32_t aK = (lane >> 4) * 16;
    const uint32_t bRowByte = (uint32_t)(wN * 32 + ((lane >> 4) << 3) + (lane & 7)) * 128;
    const uint32_t bK = ((lane >> 3) & 1) * 16;
    const uint32_t xr = (lane & 7) << 4;

    const __nv_bfloat16* __restrict__ gsrc = g_Hbf + (size_t)b * NPTS * DIM;

    const int ldRow0 = tid >> 3;               // 0..63
    const int ldSeg = tid & 7;
    const uint32_t ldDstOff = (uint32_t)(ldSeg * 16);

    auto issue_chunk = [&](int kc) {
        const uint32_t st = smA + (kc % NSTAGE) * STAGE_BYTES;
        const int kin = kc * KC + ldSeg * 8;
#pragma unroll
        for (int i = 0; i < 2; i++) {          // A: 128 rows
            int row = ldRow0 + 64 * i;
            uint32_t d = (uint32_t)row * 128 + (ldDstOff ^ ((row & 7) << 4));
            cp16(st + d, gsrc + (size_t)(rowBase + row) * DIM + kin);
        }
#pragma unroll
        for (int i = 0; i < 4; i++) {          // B: 256 rows
            int row = ldRow0 + 64 * i;
            uint32_t d = (uint32_t)row * 128 + (ldDstOff ^ ((row & 7) << 4));
            cp16(st + A_BYTES + d, gsrc + (size_t)(colBase + row) * DIM + kin);
        }
        cp_commit();
    };

    float acc[4][4][4];
#pragma unroll
    for (int mt = 0; mt < 4; mt++)
#pragma unroll
        for (int nt = 0; nt < 4; nt++)
#pragma unroll
            for (int q = 0; q < 4; q++) acc[mt][nt][q] = 0.f;

    issue_chunk(0); issue_chunk(1);

    for (int kc = 0; kc < NKC; kc++) {
        if (kc < NKC - 1) cp_wait<1>();
        else cp_wait<0>();
        __syncthreads();
        if (kc + 2 < NKC) issue_chunk(kc + 2);

        const uint32_t Ast = smA + (kc % NSTAGE) * STAGE_BYTES;
        const uint32_t Bst = Ast + A_BYTES;
#pragma unroll
        for (int ks = 0; ks < KC / 16; ks++) {
            uint32_t a[4][4], bf[2][4];
#pragma unroll
            for (int mt = 0; mt < 4; mt++)
                ldsm4(a[mt], Ast + aRowByte + mt * 2048 + ((ks * 32 + aK) ^ xr));
#pragma unroll
            for (int np = 0; np < 2; np++)
                ldsm4(bf[np], Bst + bRowByte + np * 2048 + ((ks * 32 + bK) ^ xr));
#pragma unroll
            for (int mt = 0; mt < 4; mt++)
#pragma unroll
                for (int np = 0; np < 2; np++) {
                    mma16816(acc[mt][np * 2 + 0], a[mt], bf[np][0], bf[np][1]);
                    mma16816(acc[mt][np * 2 + 1], a[mt], bf[np][2], bf[np][3]);
                }
        }
    }
    __syncthreads();   // all stages consumed; reuse stage smem as epilogue tile

    float* Ssim = (float*)dynp;                // [BM][SPAD=260]
    const int gid = lane >> 2, tig = lane & 3;
#pragma unroll
    for (int mt = 0; mt < 4; mt++) {
        const int r0 = wM * 64 + mt * 16 + gid;
#pragma unroll
        for (int nt = 0; nt < 4; nt++) {
            const int c = wN * 32 + nt * 8 + tig * 2;
            *(float2*)&Ssim[r0 * SPAD + c] = make_float2(acc[mt][nt][0], acc[mt][nt][1]);
            *(float2*)&Ssim[(r0 + 8) * SPAD + c] = make_float2(acc[mt][nt][2], acc[mt][nt][3]);
        }
    }
    __syncthreads();

    // coalesced stores: 8 row-iters x 2 col-segments of 512B
#pragma unroll
    for (int it = 0; it < 8; it++) {
        int r = it * 16 + warp;
#pragma unroll
        for (int sg = 0; sg < 2; sg++) {
            float4 v = *(const float4*)&Ssim[r * SPAD + sg * 128 + lane * 4];
            *(float4*)(out + ((size_t)b * NPTS + rowBase + r) * NPTS +
                       colBase + sg * 128 + lane * 4) = v;
        }
    }
}

// ---------------------------------------------------------------------------
// K3: per-row streaming top-12, cp.async double-buffered (one warp per row)
// ---------------------------------------------------------------------------
__global__ void __launch_bounds__(256) scan_kernel(const float* __restrict__ sim) {
    __shared__ __align__(16) float4 sbuf[8][2][SCHUNK];   // 32 KB
    const int wid = threadIdx.x >> 5;
    const int lane = threadIdx.x & 31;
    const int row = blockIdx.x * 8 + wid;
    const float4* srow = (const float4*)(sim + (size_t)row * NPTS);

    auto prefetch = [&](int ch) {
        const int buf = ch & 1;
#pragma unroll
        for (int q = 0; q < 4; q++)
            cp16(smem_u32(&sbuf[wid][buf][lane + 32 * q]), srow + ch * SCHUNK + lane + 32 * q);
        cp_commit();
    };

    const unsigned long long SENT = ((unsigned long long)fkey(-3.0e38f) << 32);
    unsigned long long L[KCAND];
#pragma unroll
    for (int j = 0; j < KCAND; j++) L[j] = SENT;
    float thresh = -3.0e38f;

    prefetch(0);
    for (int ch = 0; ch < 8; ch++) {
        if (ch + 1 < 8) { prefetch(ch + 1); cp_wait<1>(); }
        else cp_wait<0>();
        const int buf = ch & 1;
#pragma unroll
        for (int q = 0; q < 4; q++) {
            float4 v4 = sbuf[wid][buf][lane + 32 * q];
            float vv[4] = {v4.x, v4.y, v4.z, v4.w};
#pragma unroll
            for (int c = 0; c < 4; c++) {
                unsigned m = __ballot_sync(0xffffffffu, vv[c] >= thresh);
                while (m) {
                    int src = __ffs(m) - 1;
                    m &= m - 1;
                    float cv = __shfl_sync(0xffffffffu, vv[c], src);
                    if (!(cv >= thresh)) continue;
                    int ci = ch * 512 + q * 128 + src * 4 + c;
                    unsigned long long key =
                        ((unsigned long long)fkey(cv) << 32) | (uint32_t)(~ci);
                    unsigned long long carry = key;
#pragma unroll
                    for (int j = 0; j < KCAND; j++) {
                        unsigned long long hi = (carry > L[j]) ? carry : L[j];
                        unsigned long long lo = (carry > L[j]) ? L[j] : carry;
                        L[j] = hi; carry = lo;
                    }
                    thresh = unkey((uint32_t)(L[KCAND - 1] >> 32));
                }
            }
        }
    }
    if (lane == 0) {
        int* dst = g_cand + (size_t)row * KCAND;
#pragma unroll
        for (int j = 0; j < KCAND; j++)
            dst[j] = (int)(~(uint32_t)L[j]) & (NPTS - 1);
    }
}

// ---------------------------------------------------------------------------
// K4: exact fp32 rescore of 12 candidates -> top-10 (one warp per row)
// ---------------------------------------------------------------------------
__global__ void __launch_bounds__(256) rescore_kernel() {
    int gw = (blockIdx.x * blockDim.x + threadIdx.x) >> 5;
    int lane = threadIdx.x & 31;
    if (gw >= BATCH * NPTS) return;
    const int b = gw >> 12;
    const float4* base = (const float4*)(g_Hn + (size_t)b * NPTS * DIM);
    const float4* myv = (const float4*)(g_Hn + (size_t)gw * DIM);

    float4 v[4];
#pragma unroll
    for (int j = 0; j < 4; j++) v[j] = myv[lane + 32 * j];

    int ci = (lane < KCAND) ? g_cand[(size_t)gw * KCAND + lane] : 0;

    float dots[KCAND];
#pragma unroll
    for (int c = 0; c < KCAND; c++) {
        int idx = __shfl_sync(0xffffffffu, ci, c) & (NPTS - 1);
        const float4* cv = base + (size_t)idx * (DIM / 4);
        float p = 0.f;
#pragma unroll
        for (int j = 0; j < 4; j++) {
            float4 u = cv[lane + 32 * j];
            p += v[j].x * u.x + v[j].y * u.y + v[j].z * u.z + v[j].w * u.w;
        }
#pragma unroll
        for (int o = 16; o; o >>= 1) p += __shfl_xor_sync(0xffffffffu, p, o);
        dots[c] = p;
    }

    if (lane == 0) {
        float lv[K_NB]; int li[K_NB];
#pragma unroll
        for (int j = 0; j < K_NB; j++) { lv[j] = -3.0e38f; li[j] = 0x7fffffff; }
        const int* cidx = g_cand + (size_t)gw * KCAND;
#pragma unroll
        for (int c = 0; c < KCAND; c++) {
            float cv = dots[c]; int cc = cidx[c];
            if (beats(cv, cc, lv[0], li[0])) {
                int j = 0;
                while (j < K_NB - 1 && beats(cv, cc, lv[j + 1], li[j + 1])) {
                    lv[j] = lv[j + 1]; li[j] = li[j + 1]; j++;
                }
                lv[j] = cv; li[j] = cc;
            }
        }
#pragma unroll
        for (int j = 0; j < K_NB; j++) g_topk[(size_t)gw * K_NB + j] = li[j];
    }
}

// ---------------------------------------------------------------------------
// K5: fused zero + scatter (one warp per row)
//   warp zeroes its 16 KB row, __syncwarp orders, lane 0 writes 11 entries
// ---------------------------------------------------------------------------
__global__ void __launch_bounds__(256) zscatter_kernel(float* __restrict__ out) {
    int row = (blockIdx.x * blockDim.x + threadIdx.x) >> 5;
    int lane = threadIdx.x & 31;
    if (row >= BATCH * NPTS) return;
    float4* dst4 = (float4*)(out + (size_t)row * NPTS);
    const float4 z = make_float4(0.f, 0.f, 0.f, 0.f);
#pragma unroll
    for (int i = 0; i < 32; i++) dst4[lane + 32 * i] = z;
    __syncwarp();
    if (lane == 0) {
        float* dst = out + (size_t)row * NPTS;
        const int* idx = g_topk + (size_t)row * K_NB;
        const float s = 1.0f / 11.0f;
        int i = row & (NPTS - 1);
#pragma unroll
        for (int k = 0; k < K_NB; k++) dst[idx[k]] = s;
        dst[i] += s;
    }
}

// ---------------------------------------------------------------------------
extern "C" void kernel_launch(void* const* d_in, const int* in_sizes, int n_in,
                              void* d_out, int out_size) {
    const float* H = (const float*)d_in[0];
    float* out = (float*)d_out;

    norm_kernel<<<(BATCH * NPTS * 32 + 255) / 256, 256>>>(H);

    const int smem_bytes = NSTAGE * STAGE_BYTES + 1024;   // 148,480 B (epilogue fits inside)
    cudaFuncSetAttribute(gemm_kernel,
                         cudaFuncAttributeMaxDynamicSharedMemorySize, smem_bytes);
    dim3 gg(NPTS / BM, NPTS / BN, BATCH);                 // (32, 16, 4)
    gemm_kernel<<<gg, 512, smem_bytes>>>(out);            // sim -> d_out (scratch)

    scan_kernel<<<(BATCH * NPTS) / 8, 256>>>(out);

    rescore_kernel<<<(BATCH * NPTS * 32 + 255) / 256, 256>>>();

    zscatter_kernel<<<(BATCH * NPTS * 32 + 255) / 256, 256>>>(out);
}

// round 14
// speedup vs baseline: 2.5628x; 1.0634x over previous
#include <cuda_runtime.h>
#include <cuda_bf16.h>
#include <cstdint>

#define BATCH 4
#define NPTS  4096
#define DIM   512
#define K_NB  10
#define KCAND 12

#define BM 128
#define BN 256
#define KC 64                 // bf16 per K-chunk = 128 B per row
#define NSTAGE 3
#define A_BYTES (BM * 128)                  // 16 KB
#define B_BYTES (BN * 128)                  // 32 KB
#define STAGE_BYTES (A_BYTES + B_BYTES)     // 48 KB
#define NKC 8                               // DIM/KC
#define SPAD 260
#define SCHUNK 128                          // float4 per scan chunk (2 KB)

__device__ __align__(16) float g_Hn[(size_t)BATCH * NPTS * DIM];          // 32 MB fp32 normalized
__device__ __align__(16) __nv_bfloat16 g_Hbf[(size_t)BATCH * NPTS * DIM]; // 16 MB bf16
__device__ int g_cand[BATCH * NPTS * KCAND];
__device__ int g_topk[BATCH * NPTS * K_NB];

__device__ __forceinline__ uint32_t smem_u32(const void* p) {
    uint32_t a;
    asm("{ .reg .u64 t; cvta.to.shared.u64 t, %1; cvt.u32.u64 %0, t; }" : "=r"(a) : "l"(p));
    return a;
}
__device__ __forceinline__ void cp16(uint32_t dst, const void* src) {
    asm volatile("cp.async.cg.shared.global [%0], [%1], 16;" :: "r"(dst), "l"(src));
}
__device__ __forceinline__ void cp_commit() {
    asm volatile("cp.async.commit_group;" ::: "memory");
}
template <int N>
__device__ __forceinline__ void cp_wait() {
    asm volatile("cp.async.wait_group %0;" :: "n"(N) : "memory");
}
__device__ __forceinline__ void ldsm4(uint32_t* r, uint32_t addr) {
    asm volatile("ldmatrix.sync.aligned.m8n8.x4.shared.b16 {%0,%1,%2,%3}, [%4];"
                 : "=r"(r[0]), "=r"(r[1]), "=r"(r[2]), "=r"(r[3]) : "r"(addr));
}
__device__ __forceinline__ void mma16816(float* c, const uint32_t* a, uint32_t b0, uint32_t b1) {
    asm volatile(
        "mma.sync.aligned.m16n8k16.row.col.f32.bf16.bf16.f32 "
        "{%0,%1,%2,%3},{%4,%5,%6,%7},{%8,%9},{%0,%1,%2,%3};"
        : "+f"(c[0]), "+f"(c[1]), "+f"(c[2]), "+f"(c[3])
        : "r"(a[0]), "r"(a[1]), "r"(a[2]), "r"(a[3]), "r"(b0), "r"(b1));
}
__device__ __forceinline__ bool beats(float v, int vi, float w, int wi) {
    return (v > w) || (v == w && vi < wi);
}
__device__ __forceinline__ uint32_t fkey(float v) {
    uint32_t u = __float_as_uint(v);
    return (u & 0x80000000u) ? ~u : (u | 0x80000000u);
}
__device__ __forceinline__ float unkey(uint32_t u) {
    return (u & 0x80000000u) ? __uint_as_float(u & 0x7FFFFFFFu) : __uint_as_float(~u);
}

// ---------------------------------------------------------------------------
// K1: row-normalize -> fp32 g_Hn + bf16 g_Hbf (one warp per row)
// ---------------------------------------------------------------------------
__global__ void norm_kernel(const float* __restrict__ H) {
    int row = (blockIdx.x * blockDim.x + threadIdx.x) >> 5;
    int lane = threadIdx.x & 31;
    if (row >= BATCH * NPTS) return;
    const float4* src = (const float4*)(H + (size_t)row * DIM);
    float4* dstf = (float4*)(g_Hn + (size_t)row * DIM);
    __nv_bfloat16* dstb = g_Hbf + (size_t)row * DIM;
    float ss = 0.f;
    float4 v[4];
#pragma unroll
    for (int j = 0; j < 4; j++) {
        v[j] = src[lane + 32 * j];
        ss += v[j].x * v[j].x + v[j].y * v[j].y + v[j].z * v[j].z + v[j].w * v[j].w;
    }
#pragma unroll
    for (int o = 16; o; o >>= 1) ss += __shfl_xor_sync(0xffffffffu, ss, o);
    float inv = 1.0f / fmaxf(sqrtf(ss), 1e-12f);
#pragma unroll
    for (int j = 0; j < 4; j++) {
        float w[4] = {v[j].x * inv, v[j].y * inv, v[j].z * inv, v[j].w * inv};
        dstf[lane + 32 * j] = make_float4(w[0], w[1], w[2], w[3]);
        __nv_bfloat162 h0, h1;
        h0.x = __float2bfloat16_rn(w[0]); h0.y = __float2bfloat16_rn(w[1]);
        h1.x = __float2bfloat16_rn(w[2]); h1.y = __float2bfloat16_rn(w[3]);
        int off = 4 * lane + 128 * j;
        *(__nv_bfloat162*)(dstb + off) = h0;
        *(__nv_bfloat162*)(dstb + off + 2) = h1;
    }
}

// ---------------------------------------------------------------------------
// K2: bf16 mma.sync GEMM, 128x256 CTA tile, 512 threads  (R12 — unchanged)
// ---------------------------------------------------------------------------
__global__ void __launch_bounds__(512, 1) gemm_kernel(float* __restrict__ out) {
    extern __shared__ __align__(16) unsigned char rawsm[];
    unsigned char* dynp = (unsigned char*)(((uintptr_t)rawsm + 1023) & ~(uintptr_t)1023);
    const uint32_t smA = smem_u32(dynp);

    const int b = blockIdx.z;
    const int rowBase = blockIdx.x * BM;
    const int colBase = blockIdx.y * BN;
    const int tid = threadIdx.x;
    const int warp = tid >> 5, lane = tid & 31;
    const int wM = warp >> 3, wN = warp & 7;

    const uint32_t aRowByte = (uint32_t)(wM * 64 + (lane & 15)) * 128;
    const uint32_t aK = (lane >> 4) * 16;
    const uint32_t bRowByte = (uint32_t)(wN * 32 + ((lane >> 4) << 3) + (lane & 7)) * 128;
    const uint32_t bK = ((lane >> 3) & 1) * 16;
    const uint32_t xr = (lane & 7) << 4;

    const __nv_bfloat16* __restrict__ gsrc = g_Hbf + (size_t)b * NPTS * DIM;

    const int ldRow0 = tid >> 3;               // 0..63
    const int ldSeg = tid & 7;
    const uint32_t ldDstOff = (uint32_t)(ldSeg * 16);

    auto issue_chunk = [&](int kc) {
        const uint32_t st = smA + (kc % NSTAGE) * STAGE_BYTES;
        const int kin = kc * KC + ldSeg * 8;
#pragma unroll
        for (int i = 0; i < 2; i++) {          // A: 128 rows
            int row = ldRow0 + 64 * i;
            uint32_t d = (uint32_t)row * 128 + (ldDstOff ^ ((row & 7) << 4));
            cp16(st + d, gsrc + (size_t)(rowBase + row) * DIM + kin);
        }
#pragma unroll
        for (int i = 0; i < 4; i++) {          // B: 256 rows
            int row = ldRow0 + 64 * i;
            uint32_t d = (uint32_t)row * 128 + (ldDstOff ^ ((row & 7) << 4));
            cp16(st + A_BYTES + d, gsrc + (size_t)(colBase + row) * DIM + kin);
        }
        cp_commit();
    };

    float acc[4][4][4];
#pragma unroll
    for (int mt = 0; mt < 4; mt++)
#pragma unroll
        for (int nt = 0; nt < 4; nt++)
#pragma unroll
            for (int q = 0; q < 4; q++) acc[mt][nt][q] = 0.f;

    issue_chunk(0); issue_chunk(1);

    for (int kc = 0; kc < NKC; kc++) {
        if (kc < NKC - 1) cp_wait<1>();
        else cp_wait<0>();
        __syncthreads();
        if (kc + 2 < NKC) issue_chunk(kc + 2);

        const uint32_t Ast = smA + (kc % NSTAGE) * STAGE_BYTES;
        const uint32_t Bst = Ast + A_BYTES;
#pragma unroll
        for (int ks = 0; ks < KC / 16; ks++) {
            uint32_t a[4][4], bf[2][4];
#pragma unroll
            for (int mt = 0; mt < 4; mt++)
                ldsm4(a[mt], Ast + aRowByte + mt * 2048 + ((ks * 32 + aK) ^ xr));
#pragma unroll
            for (int np = 0; np < 2; np++)
                ldsm4(bf[np], Bst + bRowByte + np * 2048 + ((ks * 32 + bK) ^ xr));
#pragma unroll
            for (int mt = 0; mt < 4; mt++)
#pragma unroll
                for (int np = 0; np < 2; np++) {
                    mma16816(acc[mt][np * 2 + 0], a[mt], bf[np][0], bf[np][1]);
                    mma16816(acc[mt][np * 2 + 1], a[mt], bf[np][2], bf[np][3]);
                }
        }
    }
    __syncthreads();   // all stages consumed; reuse stage smem as epilogue tile

    float* Ssim = (float*)dynp;                // [BM][SPAD=260]
    const int gid = lane >> 2, tig = lane & 3;
#pragma unroll
    for (int mt = 0; mt < 4; mt++) {
        const int r0 = wM * 64 + mt * 16 + gid;
#pragma unroll
        for (int nt = 0; nt < 4; nt++) {
            const int c = wN * 32 + nt * 8 + tig * 2;
            *(float2*)&Ssim[r0 * SPAD + c] = make_float2(acc[mt][nt][0], acc[mt][nt][1]);
            *(float2*)&Ssim[(r0 + 8) * SPAD + c] = make_float2(acc[mt][nt][2], acc[mt][nt][3]);
        }
    }
    __syncthreads();

#pragma unroll
    for (int it = 0; it < 8; it++) {
        int r = it * 16 + warp;
#pragma unroll
        for (int sg = 0; sg < 2; sg++) {
            float4 v = *(const float4*)&Ssim[r * SPAD + sg * 128 + lane * 4];
            *(float4*)(out + ((size_t)b * NPTS + rowBase + r) * NPTS +
                       colBase + sg * 128 + lane * 4) = v;
        }
    }
}

// ---------------------------------------------------------------------------
// K3: per-row streaming top-12 (cp.async staged) + FUSED ZEROING
//   After each chunk is consumed from smem, fire-and-forget zero stores
//   to that chunk's global lines. EXPERIMENT: isolates R9's regression cause.
// ---------------------------------------------------------------------------
__global__ void __launch_bounds__(256) scan_kernel(float* __restrict__ sim) {
    __shared__ __align__(16) float4 sbuf[8][2][SCHUNK];   // 32 KB
    const int wid = threadIdx.x >> 5;
    const int lane = threadIdx.x & 31;
    const int row = blockIdx.x * 8 + wid;
    float4* srow = (float4*)(sim + (size_t)row * NPTS);

    auto prefetch = [&](int ch) {
        const int buf = ch & 1;
#pragma unroll
        for (int q = 0; q < 4; q++)
            cp16(smem_u32(&sbuf[wid][buf][lane + 32 * q]), srow + ch * SCHUNK + lane + 32 * q);
        cp_commit();
    };

    const unsigned long long SENT = ((unsigned long long)fkey(-3.0e38f) << 32);
    unsigned long long L[KCAND];
#pragma unroll
    for (int j = 0; j < KCAND; j++) L[j] = SENT;
    float thresh = -3.0e38f;
    const float4 z = make_float4(0.f, 0.f, 0.f, 0.f);

    prefetch(0);
    for (int ch = 0; ch < 8; ch++) {
        if (ch + 1 < 8) { prefetch(ch + 1); cp_wait<1>(); }
        else cp_wait<0>();
        const int buf = ch & 1;
#pragma unroll
        for (int q = 0; q < 4; q++) {
            float4 v4 = sbuf[wid][buf][lane + 32 * q];
            srow[ch * SCHUNK + lane + 32 * q] = z;   // fused zero (fire-and-forget)
            float vv[4] = {v4.x, v4.y, v4.z, v4.w};
#pragma unroll
            for (int c = 0; c < 4; c++) {
                unsigned m = __ballot_sync(0xffffffffu, vv[c] >= thresh);
                while (m) {
                    int src = __ffs(m) - 1;
                    m &= m - 1;
                    float cv = __shfl_sync(0xffffffffu, vv[c], src);
                    if (!(cv >= thresh)) continue;
                    int ci = ch * 512 + q * 128 + src * 4 + c;
                    unsigned long long key =
                        ((unsigned long long)fkey(cv) << 32) | (uint32_t)(~ci);
                    unsigned long long carry = key;
#pragma unroll
                    for (int j = 0; j < KCAND; j++) {
                        unsigned long long hi = (carry > L[j]) ? carry : L[j];
                        unsigned long long lo = (carry > L[j]) ? L[j] : carry;
                        L[j] = hi; carry = lo;
                    }
                    thresh = unkey((uint32_t)(L[KCAND - 1] >> 32));
                }
            }
        }
    }
    if (lane == 0) {
        int* dst = g_cand + (size_t)row * KCAND;
#pragma unroll
        for (int j = 0; j < KCAND; j++)
            dst[j] = (int)(~(uint32_t)L[j]) & (NPTS - 1);
    }
}

// ---------------------------------------------------------------------------
// K4: exact fp32 rescore of 12 candidates -> top-10 (one warp per row)
// ---------------------------------------------------------------------------
__global__ void __launch_bounds__(256) rescore_kernel() {
    int gw = (blockIdx.x * blockDim.x + threadIdx.x) >> 5;
    int lane = threadIdx.x & 31;
    if (gw >= BATCH * NPTS) return;
    const int b = gw >> 12;
    const float4* base = (const float4*)(g_Hn + (size_t)b * NPTS * DIM);
    const float4* myv = (const float4*)(g_Hn + (size_t)gw * DIM);

    float4 v[4];
#pragma unroll
    for (int j = 0; j < 4; j++) v[j] = myv[lane + 32 * j];

    int ci = (lane < KCAND) ? g_cand[(size_t)gw * KCAND + lane] : 0;

    float dots[KCAND];
#pragma unroll
    for (int c = 0; c < KCAND; c++) {
        int idx = __shfl_sync(0xffffffffu, ci, c) & (NPTS - 1);
        const float4* cv = base + (size_t)idx * (DIM / 4);
        float p = 0.f;
#pragma unroll
        for (int j = 0; j < 4; j++) {
            float4 u = cv[lane + 32 * j];
            p += v[j].x * u.x + v[j].y * u.y + v[j].z * u.z + v[j].w * u.w;
        }
#pragma unroll
        for (int o = 16; o; o >>= 1) p += __shfl_xor_sync(0xffffffffu, p, o);
        dots[c] = p;
    }

    if (lane == 0) {
        float lv[K_NB]; int li[K_NB];
#pragma unroll
        for (int j = 0; j < K_NB; j++) { lv[j] = -3.0e38f; li[j] = 0x7fffffff; }
        const int* cidx = g_cand + (size_t)gw * KCAND;
#pragma unroll
        for (int c = 0; c < KCAND; c++) {
            float cv = dots[c]; int cc = cidx[c];
            if (beats(cv, cc, lv[0], li[0])) {
                int j = 0;
                while (j < K_NB - 1 && beats(cv, cc, lv[j + 1], li[j + 1])) {
                    lv[j] = lv[j + 1]; li[j] = li[j + 1]; j++;
                }
                lv[j] = cv; li[j] = cc;
            }
        }
#pragma unroll
        for (int j = 0; j < K_NB; j++) g_topk[(size_t)gw * K_NB + j] = li[j];
    }
}

// ---------------------------------------------------------------------------
// K5: sparse scatter only (buffer zeroed by K3): one thread per row
// ---------------------------------------------------------------------------
__global__ void scatter_kernel(float* __restrict__ out) {
    int row = blockIdx.x * blockDim.x + threadIdx.x;
    if (row >= BATCH * NPTS) return;
    int i = row & (NPTS - 1);
    float* dst = out + (size_t)row * NPTS;
    const int* idx = g_topk + (size_t)row * K_NB;
    const float s = 1.0f / 11.0f;
#pragma unroll
    for (int k = 0; k < K_NB; k++) dst[idx[k]] = s;
    dst[i] += s;
}

// ---------------------------------------------------------------------------
extern "C" void kernel_launch(void* const* d_in, const int* in_sizes, int n_in,
                              void* d_out, int out_size) {
    const float* H = (const float*)d_in[0];
    float* out = (float*)d_out;

    norm_kernel<<<(BATCH * NPTS * 32 + 255) / 256, 256>>>(H);

    const int smem_bytes = NSTAGE * STAGE_BYTES + 1024;
    cudaFuncSetAttribute(gemm_kernel,
                         cudaFuncAttributeMaxDynamicSharedMemorySize, smem_bytes);
    dim3 gg(NPTS / BM, NPTS / BN, BATCH);                 // (32, 16, 4)
    gemm_kernel<<<gg, 512, smem_bytes>>>(out);            // sim -> d_out (scratch)

    scan_kernel<<<(BATCH * NPTS) / 8, 256>>>(out);        // top-12 + fused zero

    rescore_kernel<<<(BATCH * NPTS * 32 + 255) / 256, 256>>>();

    scatter_kernel<<<(BATCH * NPTS + 255) / 256, 256>>>(out);
}

// round 15
// speedup vs baseline: 2.9882x; 1.1660x over previous
#include <cuda_runtime.h>
#include <cuda_bf16.h>
#include <cstdint>

#define BATCH 4
#define NPTS  4096
#define DIM   512
#define K_NB  10
#define KCAND 12

#define BM 128
#define BN 256
#define KC 64                 // bf16 per K-chunk = 128 B per row
#define NSTAGE 3
#define A_BYTES (BM * 128)                  // 16 KB
#define B_BYTES (BN * 128)                  // 32 KB
#define STAGE_BYTES (A_BYTES + B_BYTES)     // 48 KB
#define NKC 8                               // DIM/KC
#define SPAD 260
#define TPAD 132
#define SCHUNK 128                          // float4 per scan chunk (2 KB)
#define NSUPER 16                           // 4096 / 256 supertiles per side
#define NTRI   136                          // NSUPER*(NSUPER+1)/2

__device__ __align__(16) float g_Hn[(size_t)BATCH * NPTS * DIM];          // 32 MB fp32 normalized
__device__ __align__(16) __nv_bfloat16 g_Hbf[(size_t)BATCH * NPTS * DIM]; // 16 MB bf16
__device__ int g_cand[BATCH * NPTS * KCAND];
__device__ int g_topk[BATCH * NPTS * K_NB];

__device__ __forceinline__ uint32_t smem_u32(const void* p) {
    uint32_t a;
    asm("{ .reg .u64 t; cvta.to.shared.u64 t, %1; cvt.u32.u64 %0, t; }" : "=r"(a) : "l"(p));
    return a;
}
__device__ __forceinline__ void cp16(uint32_t dst, const void* src) {
    asm volatile("cp.async.cg.shared.global [%0], [%1], 16;" :: "r"(dst), "l"(src));
}
__device__ __forceinline__ void cp_commit() {
    asm volatile("cp.async.commit_group;" ::: "memory");
}
template <int N>
__device__ __forceinline__ void cp_wait() {
    asm volatile("cp.async.wait_group %0;" :: "n"(N) : "memory");
}
__device__ __forceinline__ void ldsm4(uint32_t* r, uint32_t addr) {
    asm volatile("ldmatrix.sync.aligned.m8n8.x4.shared.b16 {%0,%1,%2,%3}, [%4];"
                 : "=r"(r[0]), "=r"(r[1]), "=r"(r[2]), "=r"(r[3]) : "r"(addr));
}
__device__ __forceinline__ void mma16816(float* c, const uint32_t* a, uint32_t b0, uint32_t b1) {
    asm volatile(
        "mma.sync.aligned.m16n8k16.row.col.f32.bf16.bf16.f32 "
        "{%0,%1,%2,%3},{%4,%5,%6,%7},{%8,%9},{%0,%1,%2,%3};"
        : "+f"(c[0]), "+f"(c[1]), "+f"(c[2]), "+f"(c[3])
        : "r"(a[0]), "r"(a[1]), "r"(a[2]), "r"(a[3]), "r"(b0), "r"(b1));
}
__device__ __forceinline__ bool beats(float v, int vi, float w, int wi) {
    return (v > w) || (v == w && vi < wi);
}
__device__ __forceinline__ uint32_t fkey(float v) {
    uint32_t u = __float_as_uint(v);
    return (u & 0x80000000u) ? ~u : (u | 0x80000000u);
}
__device__ __forceinline__ float unkey(uint32_t u) {
    return (u & 0x80000000u) ? __uint_as_float(u & 0x7FFFFFFFu) : __uint_as_float(~u);
}

// ---------------------------------------------------------------------------
// K1: row-normalize -> fp32 g_Hn + bf16 g_Hbf (one warp per row)
// ---------------------------------------------------------------------------
__global__ void norm_kernel(const float* __restrict__ H) {
    int row = (blockIdx.x * blockDim.x + threadIdx.x) >> 5;
    int lane = threadIdx.x & 31;
    if (row >= BATCH * NPTS) return;
    const float4* src = (const float4*)(H + (size_t)row * DIM);
    float4* dstf = (float4*)(g_Hn + (size_t)row * DIM);
    __nv_bfloat16* dstb = g_Hbf + (size_t)row * DIM;
    float ss = 0.f;
    float4 v[4];
#pragma unroll
    for (int j = 0; j < 4; j++) {
        v[j] = src[lane + 32 * j];
        ss += v[j].x * v[j].x + v[j].y * v[j].y + v[j].z * v[j].z + v[j].w * v[j].w;
    }
#pragma unroll
    for (int o = 16; o; o >>= 1) ss += __shfl_xor_sync(0xffffffffu, ss, o);
    float inv = 1.0f / fmaxf(sqrtf(ss), 1e-12f);
#pragma unroll
    for (int j = 0; j < 4; j++) {
        float w[4] = {v[j].x * inv, v[j].y * inv, v[j].z * inv, v[j].w * inv};
        dstf[lane + 32 * j] = make_float4(w[0], w[1], w[2], w[3]);
        __nv_bfloat162 h0, h1;
        h0.x = __float2bfloat16_rn(w[0]); h0.y = __float2bfloat16_rn(w[1]);
        h1.x = __float2bfloat16_rn(w[2]); h1.y = __float2bfloat16_rn(w[3]);
        int off = 4 * lane + 128 * j;
        *(__nv_bfloat162*)(dstb + off) = h0;
        *(__nv_bfloat162*)(dstb + off + 2) = h1;
    }
}

// ---------------------------------------------------------------------------
// K2: symmetric bf16 GEMM, COMPACT triangular grid (no inert CTAs).
//   grid (2*NTRI, 1, BATCH): supertile s (16x16 upper triangle) x half.
//   CTA = 128x256 tile. Off-diagonal supertiles also store the transpose
//   (second smem phase). Diagonal supertiles self-cover (two full halves).
// ---------------------------------------------------------------------------
__global__ void __launch_bounds__(512, 1) gemm_kernel(float* __restrict__ out) {
    extern __shared__ __align__(16) unsigned char rawsm[];
    unsigned char* dynp = (unsigned char*)(((uintptr_t)rawsm + 1023) & ~(uintptr_t)1023);
    const uint32_t smA = smem_u32(dynp);

    // triangular decode: blockIdx.x -> (gx, by, half), by >= gx
    int t = blockIdx.x;
    int s = t >> 1, half = t & 1;
    int gx = 0;
    while (s >= NSUPER - gx) { s -= NSUPER - gx; gx++; }
    const int by = gx + s;
    const int b = blockIdx.z;
    const int rowBase = gx * 256 + half * 128;
    const int colBase = by * 256;

    const int tid = threadIdx.x;
    const int warp = tid >> 5, lane = tid & 31;
    const int wM = warp >> 3, wN = warp & 7;

    const uint32_t aRowByte = (uint32_t)(wM * 64 + (lane & 15)) * 128;
    const uint32_t aK = (lane >> 4) * 16;
    const uint32_t bRowByte = (uint32_t)(wN * 32 + ((lane >> 4) << 3) + (lane & 7)) * 128;
    const uint32_t bK = ((lane >> 3) & 1) * 16;
    const uint32_t xr = (lane & 7) << 4;

    const __nv_bfloat16* __restrict__ gsrc = g_Hbf + (size_t)b * NPTS * DIM;

    const int ldRow0 = tid >> 3;               // 0..63
    const int ldSeg = tid & 7;
    const uint32_t ldDstOff = (uint32_t)(ldSeg * 16);

    auto issue_chunk = [&](int kc) {
        const uint32_t st = smA + (kc % NSTAGE) * STAGE_BYTES;
        const int kin = kc * KC + ldSeg * 8;
#pragma unroll
        for (int i = 0; i < 2; i++) {          // A: 128 rows
            int row = ldRow0 + 64 * i;
            uint32_t d = (uint32_t)row * 128 + (ldDstOff ^ ((row & 7) << 4));
            cp16(st + d, gsrc + (size_t)(rowBase + row) * DIM + kin);
        }
#pragma unroll
        for (int i = 0; i < 4; i++) {          // B: 256 rows
            int row = ldRow0 + 64 * i;
            uint32_t d = (uint32_t)row * 128 + (ldDstOff ^ ((row & 7) << 4));
            cp16(st + A_BYTES + d, gsrc + (size_t)(colBase + row) * DIM + kin);
        }
        cp_commit();
    };

    float acc[4][4][4];
#pragma unroll
    for (int mt = 0; mt < 4; mt++)
#pragma unroll
        for (int nt = 0; nt < 4; nt++)
#pragma unroll
            for (int q = 0; q < 4; q++) acc[mt][nt][q] = 0.f;

    issue_chunk(0); issue_chunk(1);

    for (int kc = 0; kc < NKC; kc++) {
        if (kc < NKC - 1) cp_wait<1>();
        else cp_wait<0>();
        __syncthreads();
        if (kc + 2 < NKC) issue_chunk(kc + 2);

        const uint32_t Ast = smA + (kc % NSTAGE) * STAGE_BYTES;
        const uint32_t Bst = Ast + A_BYTES;
#pragma unroll
        for (int ks = 0; ks < KC / 16; ks++) {
            uint32_t a[4][4], bf[2][4];
#pragma unroll
            for (int mt = 0; mt < 4; mt++)
                ldsm4(a[mt], Ast + aRowByte + mt * 2048 + ((ks * 32 + aK) ^ xr));
#pragma unroll
            for (int np = 0; np < 2; np++)
                ldsm4(bf[np], Bst + bRowByte + np * 2048 + ((ks * 32 + bK) ^ xr));
#pragma unroll
            for (int mt = 0; mt < 4; mt++)
#pragma unroll
                for (int np = 0; np < 2; np++) {
                    mma16816(acc[mt][np * 2 + 0], a[mt], bf[np][0], bf[np][1]);
                    mma16816(acc[mt][np * 2 + 1], a[mt], bf[np][2], bf[np][3]);
                }
        }
    }
    __syncthreads();   // stages consumed; reuse stage smem as epilogue scratch

    const int gid = lane >> 2, tig = lane & 3;

    // ---- phase 1: normal tile [BM][SPAD] ----
    {
        float* Ssim = (float*)dynp;
#pragma unroll
        for (int mt = 0; mt < 4; mt++) {
            const int r0 = wM * 64 + mt * 16 + gid;
#pragma unroll
            for (int nt = 0; nt < 4; nt++) {
                const int c = wN * 32 + nt * 8 + tig * 2;
                *(float2*)&Ssim[r0 * SPAD + c] = make_float2(acc[mt][nt][0], acc[mt][nt][1]);
                *(float2*)&Ssim[(r0 + 8) * SPAD + c] = make_float2(acc[mt][nt][2], acc[mt][nt][3]);
            }
        }
        __syncthreads();
#pragma unroll
        for (int it = 0; it < 8; it++) {
            int r = it * 16 + warp;
#pragma unroll
            for (int sg = 0; sg < 2; sg++) {
                float4 v = *(const float4*)&Ssim[r * SPAD + sg * 128 + lane * 4];
                *(float4*)(out + ((size_t)b * NPTS + rowBase + r) * NPTS +
                           colBase + sg * 128 + lane * 4) = v;
            }
        }
    }

    // ---- phase 2: transposed tile [BN][TPAD] (off-diagonal supertiles only) ----
    if (by != gx) {
        __syncthreads();
        float* SsimT = (float*)dynp;
#pragma unroll
        for (int mt = 0; mt < 4; mt++) {
            const int r0 = wM * 64 + mt * 16 + gid;
#pragma unroll
            for (int nt = 0; nt < 4; nt++) {
                const int c = wN * 32 + nt * 8 + tig * 2;
                SsimT[(c + 0) * TPAD + r0]     = acc[mt][nt][0];
                SsimT[(c + 1) * TPAD + r0]     = acc[mt][nt][1];
                SsimT[(c + 0) * TPAD + r0 + 8] = acc[mt][nt][2];
                SsimT[(c + 1) * TPAD + r0 + 8] = acc[mt][nt][3];
            }
        }
        __syncthreads();
#pragma unroll
        for (int it = 0; it < 16; it++) {
            int r = it * 16 + warp;
            float4 v = *(const float4*)&SsimT[r * TPAD + lane * 4];
            *(float4*)(out + ((size_t)b * NPTS + colBase + r) * NPTS +
                       rowBase + lane * 4) = v;
        }
    }
}

// ---------------------------------------------------------------------------
// K3: per-row streaming top-12 (cp.async staged) + fused zeroing (proven R14)
// ---------------------------------------------------------------------------
__global__ void __launch_bounds__(256) scan_kernel(float* __restrict__ sim) {
    __shared__ __align__(16) float4 sbuf[8][2][SCHUNK];   // 32 KB
    const int wid = threadIdx.x >> 5;
    const int lane = threadIdx.x & 31;
    const int row = blockIdx.x * 8 + wid;
    float4* srow = (float4*)(sim + (size_t)row * NPTS);

    auto prefetch = [&](int ch) {
        const int buf = ch & 1;
#pragma unroll
        for (int q = 0; q < 4; q++)
            cp16(smem_u32(&sbuf[wid][buf][lane + 32 * q]), srow + ch * SCHUNK + lane + 32 * q);
        cp_commit();
    };

    const unsigned long long SENT = ((unsigned long long)fkey(-3.0e38f) << 32);
    unsigned long long L[KCAND];
#pragma unroll
    for (int j = 0; j < KCAND; j++) L[j] = SENT;
    float thresh = -3.0e38f;
    const float4 z = make_float4(0.f, 0.f, 0.f, 0.f);

    prefetch(0);
    for (int ch = 0; ch < 8; ch++) {
        if (ch + 1 < 8) { prefetch(ch + 1); cp_wait<1>(); }
        else cp_wait<0>();
        const int buf = ch & 1;
#pragma unroll
        for (int q = 0; q < 4; q++) {
            float4 v4 = sbuf[wid][buf][lane + 32 * q];
            srow[ch * SCHUNK + lane + 32 * q] = z;   // fused zero (fire-and-forget)
            float vv[4] = {v4.x, v4.y, v4.z, v4.w};
#pragma unroll
            for (int c = 0; c < 4; c++) {
                unsigned m = __ballot_sync(0xffffffffu, vv[c] >= thresh);
                while (m) {
                    int src = __ffs(m) - 1;
                    m &= m - 1;
                    float cv = __shfl_sync(0xffffffffu, vv[c], src);
                    if (!(cv >= thresh)) continue;
                    int ci = ch * 512 + q * 128 + src * 4 + c;
                    unsigned long long key =
                        ((unsigned long long)fkey(cv) << 32) | (uint32_t)(~ci);
                    unsigned long long carry = key;
#pragma unroll
                    for (int j = 0; j < KCAND; j++) {
                        unsigned long long hi = (carry > L[j]) ? carry : L[j];
                        unsigned long long lo = (carry > L[j]) ? L[j] : carry;
                        L[j] = hi; carry = lo;
                    }
                    thresh = unkey((uint32_t)(L[KCAND - 1] >> 32));
                }
            }
        }
    }
    if (lane == 0) {
        int* dst = g_cand + (size_t)row * KCAND;
#pragma unroll
        for (int j = 0; j < KCAND; j++)
            dst[j] = (int)(~(uint32_t)L[j]) & (NPTS - 1);
    }
}

// ---------------------------------------------------------------------------
// K4: exact fp32 rescore of 12 candidates -> top-10 (one warp per row)
// ---------------------------------------------------------------------------
__global__ void __launch_bounds__(256) rescore_kernel() {
    int gw = (blockIdx.x * blockDim.x + threadIdx.x) >> 5;
    int lane = threadIdx.x & 31;
    if (gw >= BATCH * NPTS) return;
    const int b = gw >> 12;
    const float4* base = (const float4*)(g_Hn + (size_t)b * NPTS * DIM);
    const float4* myv = (const float4*)(g_Hn + (size_t)gw * DIM);

    float4 v[4];
#pragma unroll
    for (int j = 0; j < 4; j++) v[j] = myv[lane + 32 * j];

    int ci = (lane < KCAND) ? g_cand[(size_t)gw * KCAND + lane] : 0;

    float dots[KCAND];
#pragma unroll
    for (int c = 0; c < KCAND; c++) {
        int idx = __shfl_sync(0xffffffffu, ci, c) & (NPTS - 1);
        const float4* cv = base + (size_t)idx * (DIM / 4);
        float p = 0.f;
#pragma unroll
        for (int j = 0; j < 4; j++) {
            float4 u = cv[lane + 32 * j];
            p += v[j].x * u.x + v[j].y * u.y + v[j].z * u.z + v[j].w * u.w;
        }
#pragma unroll
        for (int o = 16; o; o >>= 1) p += __shfl_xor_sync(0xffffffffu, p, o);
        dots[c] = p;
    }

    if (lane == 0) {
        float lv[K_NB]; int li[K_NB];
#pragma unroll
        for (int j = 0; j < K_NB; j++) { lv[j] = -3.0e38f; li[j] = 0x7fffffff; }
        const int* cidx = g_cand + (size_t)gw * KCAND;
#pragma unroll
        for (int c = 0; c < KCAND; c++) {
            float cv = dots[c]; int cc = cidx[c];
            if (beats(cv, cc, lv[0], li[0])) {
                int j = 0;
                while (j < K_NB - 1 && beats(cv, cc, lv[j + 1], li[j + 1])) {
                    lv[j] = lv[j + 1]; li[j] = li[j + 1]; j++;
                }
                lv[j] = cv; li[j] = cc;
            }
        }
#pragma unroll
        for (int j = 0; j < K_NB; j++) g_topk[(size_t)gw * K_NB + j] = li[j];
    }
}

// ---------------------------------------------------------------------------
// K5: sparse scatter only (buffer zeroed by K3): one thread per row
// ---------------------------------------------------------------------------
__global__ void scatter_kernel(float* __restrict__ out) {
    int row = blockIdx.x * blockDim.x + threadIdx.x;
    if (row >= BATCH * NPTS) return;
    int i = row & (NPTS - 1);
    float* dst = out + (size_t)row * NPTS;
    const int* idx = g_topk + (size_t)row * K_NB;
    const float s = 1.0f / 11.0f;
#pragma unroll
    for (int k = 0; k < K_NB; k++) dst[idx[k]] = s;
    dst[i] += s;
}

// ---------------------------------------------------------------------------
extern "C" void kernel_launch(void* const* d_in, const int* in_sizes, int n_in,
                              void* d_out, int out_size) {
    const float* H = (const float*)d_in[0];
    float* out = (float*)d_out;

    norm_kernel<<<(BATCH * NPTS * 32 + 255) / 256, 256>>>(H);

    const int smem_bytes = NSTAGE * STAGE_BYTES + 1024;   // 148 KB; epilogue phases fit inside
    cudaFuncSetAttribute(gemm_kernel,
                         cudaFuncAttributeMaxDynamicSharedMemorySize, smem_bytes);
    dim3 gg(2 * NTRI, 1, BATCH);                          // (272, 1, 4) — only working tiles
    gemm_kernel<<<gg, 512, smem_bytes>>>(out);            // sim -> d_out (scratch)

    scan_kernel<<<(BATCH * NPTS) / 8, 256>>>(out);        // top-12 + fused zero

    rescore_kernel<<<(BATCH * NPTS * 32 + 255) / 256, 256>>>();

    scatter_kernel<<<(BATCH * NPTS + 255) / 256, 256>>>(out);
}